// round 1
// baseline (speedup 1.0000x reference)
#include <cuda_runtime.h>
#include <math.h>

// ---------------------------------------------------------------------------
// Problem constants
//   x  : [4, 1024, 1024]  -> flattened [4096, 1024]
//   Wq/Wk/Wv/Wo : [1024, 1024], applied as x @ W^T  (NT gemm, both K-major)
//   bo : [1024]
//   heads = 16, d_k = 64
// ---------------------------------------------------------------------------

#define M_ROWS 4096
#define K_DIM  1024
#define N_DIM  1024
#define HEADS  16
#define DHEAD  64
#define TSEQ   1024
#define BATCH  4

// Scratch (allocation-free rule: __device__ globals)
__device__ float g_Q[M_ROWS * K_DIM];
__device__ float g_K[M_ROWS * K_DIM];
__device__ float g_V[M_ROWS * K_DIM];
__device__ float g_A[M_ROWS * K_DIM];   // attention output, [b, t, h*d] layout

// ---------------------------------------------------------------------------
// SGEMM NT: C[M,N] = A[M,K] * B[N,K]^T (+ bias[N])
// 128x128 tile, BK=16, 256 threads, 8x8 per-thread micro-tile.
// ---------------------------------------------------------------------------
#define GM_BM 128
#define GM_BN 128
#define GM_BK 16

__device__ __forceinline__ void gemm_nt_body(
    const float* __restrict__ A, const float* __restrict__ B,
    const float* __restrict__ bias, float* __restrict__ C,
    int N, int K,
    float (*As)[GM_BM], float (*Bs)[GM_BN])
{
    const int tid = threadIdx.x;
    const int ty  = tid >> 4;        // 0..15
    const int tx  = tid & 15;        // 0..15
    const int bm  = blockIdx.y * GM_BM;
    const int bn  = blockIdx.x * GM_BN;

    // global-load mapping: 256 threads fetch 128x16 floats per operand
    const int lr = tid >> 2;         // 0..63
    const int lc = (tid & 3) << 2;   // 0,4,8,12

    const float* Ag = A + (bm + lr) * K + lc;
    const float* Bg = B + (bn + lr) * K + lc;

    float acc[8][8];
#pragma unroll
    for (int i = 0; i < 8; i++)
#pragma unroll
        for (int j = 0; j < 8; j++) acc[i][j] = 0.f;

    for (int k0 = 0; k0 < K; k0 += GM_BK) {
        float4 a0 = *(const float4*)(Ag + k0);
        float4 a1 = *(const float4*)(Ag + 64 * K + k0);
        float4 b0 = *(const float4*)(Bg + k0);
        float4 b1 = *(const float4*)(Bg + 64 * K + k0);

        // store transposed: As[k][m]
        As[lc + 0][lr] = a0.x; As[lc + 1][lr] = a0.y;
        As[lc + 2][lr] = a0.z; As[lc + 3][lr] = a0.w;
        As[lc + 0][lr + 64] = a1.x; As[lc + 1][lr + 64] = a1.y;
        As[lc + 2][lr + 64] = a1.z; As[lc + 3][lr + 64] = a1.w;

        Bs[lc + 0][lr] = b0.x; Bs[lc + 1][lr] = b0.y;
        Bs[lc + 2][lr] = b0.z; Bs[lc + 3][lr] = b0.w;
        Bs[lc + 0][lr + 64] = b1.x; Bs[lc + 1][lr + 64] = b1.y;
        Bs[lc + 2][lr + 64] = b1.z; Bs[lc + 3][lr + 64] = b1.w;

        __syncthreads();

#pragma unroll
        for (int kk = 0; kk < GM_BK; kk++) {
            float a[8], b[8];
            *(float4*)&a[0] = *(const float4*)&As[kk][ty * 4];
            *(float4*)&a[4] = *(const float4*)&As[kk][ty * 4 + 64];
            *(float4*)&b[0] = *(const float4*)&Bs[kk][tx * 4];
            *(float4*)&b[4] = *(const float4*)&Bs[kk][tx * 4 + 64];
#pragma unroll
            for (int i = 0; i < 8; i++)
#pragma unroll
                for (int j = 0; j < 8; j++)
                    acc[i][j] = fmaf(a[i], b[j], acc[i][j]);
        }
        __syncthreads();
    }

    // write 8x8 as 2x4 rows x 2 float4 cols
#pragma unroll
    for (int io = 0; io < 2; io++) {
#pragma unroll
        for (int ii = 0; ii < 4; ii++) {
            const int row = bm + io * 64 + ty * 4 + ii;
#pragma unroll
            for (int jo = 0; jo < 2; jo++) {
                const int col = bn + jo * 64 + tx * 4;
                float4 v;
                v.x = acc[io * 4 + ii][jo * 4 + 0];
                v.y = acc[io * 4 + ii][jo * 4 + 1];
                v.z = acc[io * 4 + ii][jo * 4 + 2];
                v.w = acc[io * 4 + ii][jo * 4 + 3];
                if (bias) {
                    v.x += bias[col + 0];
                    v.y += bias[col + 1];
                    v.z += bias[col + 2];
                    v.w += bias[col + 3];
                }
                *(float4*)&C[row * N + col] = v;
            }
        }
    }
}

// QKV projections in one launch: blockIdx.z selects weight/output
__global__ __launch_bounds__(256) void qkv_kernel(
    const float* __restrict__ x,
    const float* __restrict__ Wq,
    const float* __restrict__ Wk,
    const float* __restrict__ Wv,
    int N, int K)
{
    __shared__ float As[GM_BK][GM_BM];
    __shared__ float Bs[GM_BK][GM_BN];
    const float* B;
    float* C;
    if (blockIdx.z == 0)      { B = Wq; C = g_Q; }
    else if (blockIdx.z == 1) { B = Wk; C = g_K; }
    else                      { B = Wv; C = g_V; }
    gemm_nt_body(x, B, nullptr, C, N, K, As, Bs);
}

// Output projection: out = g_A @ Wo^T + bo
__global__ __launch_bounds__(256) void out_gemm_kernel(
    const float* __restrict__ Wo,
    const float* __restrict__ bo,
    float* __restrict__ out,
    int N, int K)
{
    __shared__ float As[GM_BK][GM_BM];
    __shared__ float Bs[GM_BK][GM_BN];
    gemm_nt_body(g_A, Wo, bo, out, N, K, As, Bs);
}

// ---------------------------------------------------------------------------
// Attention: one CTA per (b,h, 64-query tile). Flash-style online softmax.
// Smem: Qst [64][64] (transposed, Qst[k][m]), Ks [64][65] (padded; reused
// as P), Vs [64][64]. 256 threads = 16x16, 4x4 micro-tile per thread.
// ---------------------------------------------------------------------------
#define LDK 65
#define ATTN_SMEM_BYTES ((64*64 + 64*LDK + 64*64) * 4)

__global__ __launch_bounds__(256) void attn_kernel()
{
    extern __shared__ float sm[];
    float* Qst = sm;                       // [64][64]  Qst[kk*64 + m]
    float* Ks  = sm + 64 * 64;             // [64][65]  Ks[r*65 + kk]; reused as P
    float* Vs  = sm + 64 * 64 + 64 * LDK;  // [64][64]  Vs[kk*64 + d]

    const int qt  = blockIdx.x;            // 0..15 query tile
    const int bh  = blockIdx.y;            // 0..63
    const int b   = bh >> 4;
    const int h   = bh & 15;
    const int tid = threadIdx.x;
    const int ty  = tid >> 4;
    const int tx  = tid & 15;

    const int qrow0 = b * TSEQ + qt * 64;  // global row of first query
    const int cbase = h * DHEAD;           // column offset of this head

    // load Q tile transposed: Qst[c][r] = Q[qrow0+r][cbase+c]
    for (int i = tid; i < 64 * 16; i += 256) {
        const int r  = i >> 4;
        const int c4 = (i & 15) << 2;
        float4 v = *(const float4*)&g_Q[(qrow0 + r) * K_DIM + cbase + c4];
        Qst[(c4 + 0) * 64 + r] = v.x;
        Qst[(c4 + 1) * 64 + r] = v.y;
        Qst[(c4 + 2) * 64 + r] = v.z;
        Qst[(c4 + 3) * 64 + r] = v.w;
    }

    float acc[4][4];
    float m_i[4], l_i[4];
#pragma unroll
    for (int i = 0; i < 4; i++) {
        m_i[i] = -INFINITY; l_i[i] = 0.f;
#pragma unroll
        for (int j = 0; j < 4; j++) acc[i][j] = 0.f;
    }

    for (int kt = 0; kt < 16; kt++) {
        __syncthreads();   // prior iteration's P/V readers done (also orders Q store)
        const int krow0 = b * TSEQ + kt * 64;
        for (int i = tid; i < 64 * 16; i += 256) {
            const int r  = i >> 4;
            const int c4 = (i & 15) << 2;
            float4 kv = *(const float4*)&g_K[(krow0 + r) * K_DIM + cbase + c4];
            Ks[r * LDK + c4 + 0] = kv.x;
            Ks[r * LDK + c4 + 1] = kv.y;
            Ks[r * LDK + c4 + 2] = kv.z;
            Ks[r * LDK + c4 + 3] = kv.w;
            float4 vv = *(const float4*)&g_V[(krow0 + r) * K_DIM + cbase + c4];
            *(float4*)&Vs[r * 64 + c4] = vv;
        }
        __syncthreads();

        // S = Q K^T for this tile: s[i][j], rows ty*4+i, keys tx*4+j
        float s[4][4];
#pragma unroll
        for (int i = 0; i < 4; i++)
#pragma unroll
            for (int j = 0; j < 4; j++) s[i][j] = 0.f;

#pragma unroll 8
        for (int kk = 0; kk < 64; kk++) {
            float qv[4];
            *(float4*)qv = *(const float4*)&Qst[kk * 64 + ty * 4];
            float bv[4];
            bv[0] = Ks[(tx * 4 + 0) * LDK + kk];
            bv[1] = Ks[(tx * 4 + 1) * LDK + kk];
            bv[2] = Ks[(tx * 4 + 2) * LDK + kk];
            bv[3] = Ks[(tx * 4 + 3) * LDK + kk];
#pragma unroll
            for (int i = 0; i < 4; i++)
#pragma unroll
                for (int j = 0; j < 4; j++)
                    s[i][j] = fmaf(qv[i], bv[j], s[i][j]);
        }

        // online softmax update (row groups = same ty = 16 aligned lanes)
#pragma unroll
        for (int i = 0; i < 4; i++) {
            float rm = -INFINITY;
#pragma unroll
            for (int j = 0; j < 4; j++) {
                s[i][j] *= 0.125f;                 // 1/sqrt(64)
                rm = fmaxf(rm, s[i][j]);
            }
#pragma unroll
            for (int off = 8; off > 0; off >>= 1)
                rm = fmaxf(rm, __shfl_xor_sync(0xffffffffu, rm, off));
            const float nm    = fmaxf(m_i[i], rm);
            const float alpha = __expf(m_i[i] - nm);
            float rs = 0.f;
#pragma unroll
            for (int j = 0; j < 4; j++) {
                s[i][j] = __expf(s[i][j] - nm);
                rs += s[i][j];
            }
#pragma unroll
            for (int off = 8; off > 0; off >>= 1)
                rs += __shfl_xor_sync(0xffffffffu, rs, off);
            l_i[i] = l_i[i] * alpha + rs;
            m_i[i] = nm;
#pragma unroll
            for (int j = 0; j < 4; j++) acc[i][j] *= alpha;
        }

        // stage P into Ks buffer (everyone done reading Ks)
        __syncthreads();
#pragma unroll
        for (int i = 0; i < 4; i++)
#pragma unroll
            for (int j = 0; j < 4; j++)
                Ks[(ty * 4 + i) * LDK + tx * 4 + j] = s[i][j];
        __syncthreads();

        // O += P @ V
#pragma unroll 8
        for (int kk = 0; kk < 64; kk++) {
            float vv[4];
            *(float4*)vv = *(const float4*)&Vs[kk * 64 + tx * 4];
            float pv[4];
            pv[0] = Ks[(ty * 4 + 0) * LDK + kk];
            pv[1] = Ks[(ty * 4 + 1) * LDK + kk];
            pv[2] = Ks[(ty * 4 + 2) * LDK + kk];
            pv[3] = Ks[(ty * 4 + 3) * LDK + kk];
#pragma unroll
            for (int i = 0; i < 4; i++)
#pragma unroll
                for (int j = 0; j < 4; j++)
                    acc[i][j] = fmaf(pv[i], vv[j], acc[i][j]);
        }
    }

    // normalize and write to g_A in [b, t, h*d + d'] layout
#pragma unroll
    for (int i = 0; i < 4; i++) {
        const float inv = 1.0f / l_i[i];
        float4 o;
        o.x = acc[i][0] * inv;
        o.y = acc[i][1] * inv;
        o.z = acc[i][2] * inv;
        o.w = acc[i][3] * inv;
        *(float4*)&g_A[(qrow0 + ty * 4 + i) * K_DIM + cbase + tx * 4] = o;
    }
}

// ---------------------------------------------------------------------------
// kernel_launch
// ---------------------------------------------------------------------------
extern "C" void kernel_launch(void* const* d_in, const int* in_sizes, int n_in,
                              void* d_out, int out_size)
{
    const float* x  = (const float*)d_in[0];
    const float* Wq = (const float*)d_in[1];
    const float* Wk = (const float*)d_in[2];
    const float* Wv = (const float*)d_in[3];
    const float* Wo = (const float*)d_in[4];
    const float* bo = (const float*)d_in[5];
    float* out = (float*)d_out;

    dim3 blk(256);

    // 1) Q/K/V projections (one launch, z selects weight)
    dim3 grid_qkv(N_DIM / GM_BN, M_ROWS / GM_BM, 3);
    qkv_kernel<<<grid_qkv, blk>>>(x, Wq, Wk, Wv, N_DIM, K_DIM);

    // 2) attention
    cudaFuncSetAttribute(attn_kernel,
                         cudaFuncAttributeMaxDynamicSharedMemorySize,
                         ATTN_SMEM_BYTES);
    attn_kernel<<<dim3(16, BATCH * HEADS), blk, ATTN_SMEM_BYTES>>>();

    // 3) output projection + bias
    dim3 grid_o(N_DIM / GM_BN, M_ROWS / GM_BM);
    out_gemm_kernel<<<grid_o, blk>>>(Wo, bo, out, N_DIM, K_DIM);
}

// round 4
// speedup vs baseline: 1.3008x; 1.3008x over previous
#include <cuda_runtime.h>
#include <cuda_bf16.h>
#include <math.h>
#include <stdint.h>

// ---------------------------------------------------------------------------
// Problem constants
//   x : [4,1024,1024] -> [4096,1024];  Wq/Wk/Wv/Wo : [1024,1024] (x @ W^T)
// ---------------------------------------------------------------------------
#define M_ROWS 4096
#define K_DIM  1024
#define N_DIM  1024
#define HEADS  16
#define DHEAD  64
#define TSEQ   1024
#define BATCH  4

// split-bf16 widened K:  A' = [Ahi | Ahi | Alo],  B' = [Bhi | Blo | Bhi]
#define KP     3072

// fp32 scratch
__device__ float g_Q[M_ROWS * K_DIM];
__device__ float g_K[M_ROWS * K_DIM];
__device__ float g_V[M_ROWS * K_DIM];
__device__ float g_A[M_ROWS * K_DIM];

// split-bf16 scratch (K' = 3072 layouts)
__device__ __align__(16) __nv_bfloat16 g_xs[M_ROWS * KP];          // A' for QKV
__device__ __align__(16) __nv_bfloat16 g_As[M_ROWS * KP];          // A' for out-proj
__device__ __align__(16) __nv_bfloat16 g_Ws[4 * N_DIM * KP];       // B' per weight

// ---------------------------------------------------------------------------
// PTX helpers (base sm_103 target: cp.async + ldmatrix + mma.sync bf16)
// ---------------------------------------------------------------------------
__device__ __forceinline__ uint32_t smem_u32(const void* p) {
    uint32_t a;
    asm("{ .reg .u64 t; cvta.to.shared.u64 t, %1; cvt.u32.u64 %0, t; }"
        : "=r"(a) : "l"(p));
    return a;
}
__device__ __forceinline__ void cp16(uint32_t s, const void* g) {
    asm volatile("cp.async.cg.shared.global [%0], [%1], 16;" :: "r"(s), "l"(g));
}
#define CP_COMMIT() asm volatile("cp.async.commit_group;" ::: "memory")
#define CP_WAIT(n)  asm volatile("cp.async.wait_group %0;" :: "n"(n) : "memory")

#define LDSM_X4(r, addr)                                                       \
    asm volatile("ldmatrix.sync.aligned.m8n8.x4.shared.b16 {%0,%1,%2,%3}, [%4];" \
                 : "=r"((r)[0]), "=r"((r)[1]), "=r"((r)[2]), "=r"((r)[3])      \
                 : "r"(addr))

__device__ __forceinline__ void mma16816(float* c, const uint32_t* a,
                                         const uint32_t* b) {
    asm volatile(
        "mma.sync.aligned.m16n8k16.row.col.f32.bf16.bf16.f32 "
        "{%0,%1,%2,%3}, {%4,%5,%6,%7}, {%8,%9}, {%0,%1,%2,%3};"
        : "+f"(c[0]), "+f"(c[1]), "+f"(c[2]), "+f"(c[3])
        : "r"(a[0]), "r"(a[1]), "r"(a[2]), "r"(a[3]), "r"(b[0]), "r"(b[1]));
}

// ---------------------------------------------------------------------------
// HMMA bf16 NT GEMM: C[M,N] = A'[M,KP] @ B'[N,KP]^T (+ bias)
// CTA 128x128, BK=64, 256 threads = 8 warps (2 M x 4 N), warp tile 64x32.
// Smem rows padded to 72 bf16 (144B stride -> conflict-free ldmatrix).
// ---------------------------------------------------------------------------
#define GBM 128
#define GBN 128
#define GBK 64
#define LDA 72
#define STAGE_ELEMS (128 * LDA)
#define NCH (KP / GBK)                 // 48
#define GEMM_SMEM (4 * STAGE_ELEMS * 2)  // 2 bufs x (A+B) x bf16 = 73728B

__device__ __forceinline__ void load_chunk(const __nv_bfloat16* __restrict__ A,
                                           const __nv_bfloat16* __restrict__ B,
                                           int bm, int bn, int k0,
                                           uint32_t sA, uint32_t sB) {
    const int tid = threadIdx.x;
#pragma unroll
    for (int i = 0; i < 4; i++) {
        const int idx = tid * 4 + i;           // 0..1023
        const int row = idx >> 3;
        const int seg = idx & 7;
        cp16(sA + (row * LDA + seg * 8) * 2,
             A + (size_t)(bm + row) * KP + k0 + seg * 8);
        cp16(sB + (row * LDA + seg * 8) * 2,
             B + (size_t)(bn + row) * KP + k0 + seg * 8);
    }
    CP_COMMIT();
}

__device__ void gemm_hmma_body(const __nv_bfloat16* __restrict__ A,
                               const __nv_bfloat16* __restrict__ B,
                               const float* __restrict__ bias,
                               float* __restrict__ C) {
    extern __shared__ char sm[];
    const uint32_t smb = smem_u32(sm);
    const uint32_t sA0 = smb;
    const uint32_t sB0 = smb + 2 * STAGE_ELEMS * 2;   // after 2 A stages

    const int tid  = threadIdx.x;
    const int wid  = tid >> 5;
    const int lane = tid & 31;
    const int wm   = wid >> 2;       // 0..1
    const int wn   = wid & 3;        // 0..3
    const int bm   = blockIdx.y * GBM;
    const int bn   = blockIdx.x * GBN;

    float acc[4][4][4];
#pragma unroll
    for (int i = 0; i < 4; i++)
#pragma unroll
        for (int j = 0; j < 4; j++)
#pragma unroll
            for (int r = 0; r < 4; r++) acc[i][j][r] = 0.f;

    load_chunk(A, B, bm, bn, 0, sA0, sB0);

    for (int c = 0; c < NCH; c++) {
        const int buf = c & 1;
        if (c + 1 < NCH) {
            load_chunk(A, B, bm, bn, (c + 1) * GBK,
                       sA0 + ((c + 1) & 1) * STAGE_ELEMS * 2,
                       sB0 + ((c + 1) & 1) * STAGE_ELEMS * 2);
            CP_WAIT(1);
        } else {
            CP_WAIT(0);
        }
        __syncthreads();

        const uint32_t aB = sA0 + buf * STAGE_ELEMS * 2;
        const uint32_t bB = sB0 + buf * STAGE_ELEMS * 2;

#pragma unroll
        for (int ks = 0; ks < 4; ks++) {
            uint32_t afr[4][4];
#pragma unroll
            for (int mi = 0; mi < 4; mi++) {
                const int row = wm * 64 + mi * 16 + (lane & 15);
                const int col = ks * 16 + (lane >> 4) * 8;
                LDSM_X4(afr[mi], aB + (row * LDA + col) * 2);
            }
            uint32_t bfr[2][4];
#pragma unroll
            for (int np = 0; np < 2; np++) {
                const int g   = lane >> 3;
                const int row = wn * 32 + np * 16 + (g >> 1) * 8 + (lane & 7);
                const int col = ks * 16 + (g & 1) * 8;
                LDSM_X4(bfr[np], bB + (row * LDA + col) * 2);
            }
#pragma unroll
            for (int mi = 0; mi < 4; mi++) {
#pragma unroll
                for (int ni = 0; ni < 4; ni++)
                    mma16816(acc[mi][ni], afr[mi], &bfr[ni >> 1][(ni & 1) * 2]);
            }
        }
        __syncthreads();
    }

    // epilogue: direct float2 stores
#pragma unroll
    for (int mi = 0; mi < 4; mi++) {
#pragma unroll
        for (int ni = 0; ni < 4; ni++) {
            const int r0 = bm + wm * 64 + mi * 16 + (lane >> 2);
            const int c0 = bn + wn * 32 + ni * 8 + (lane & 3) * 2;
            float2 v0 = make_float2(acc[mi][ni][0], acc[mi][ni][1]);
            float2 v1 = make_float2(acc[mi][ni][2], acc[mi][ni][3]);
            if (bias) {
                const float b0 = bias[c0], b1 = bias[c0 + 1];
                v0.x += b0; v0.y += b1;
                v1.x += b0; v1.y += b1;
            }
            *(float2*)&C[(size_t)r0 * N_DIM + c0]       = v0;
            *(float2*)&C[(size_t)(r0 + 8) * N_DIM + c0] = v1;
        }
    }
}

__global__ __launch_bounds__(256) void qkv_hmma_kernel() {
    const int z = blockIdx.z;
    float* C = (z == 0) ? g_Q : (z == 1) ? g_K : g_V;
    gemm_hmma_body(g_xs, g_Ws + (size_t)z * N_DIM * KP, nullptr, C);
}

__global__ __launch_bounds__(256) void out_hmma_kernel(const float* __restrict__ bo,
                                                       float* __restrict__ out) {
    gemm_hmma_body(g_As, g_Ws + (size_t)3 * N_DIM * KP, bo, out);
}

// ---------------------------------------------------------------------------
// fp32 -> split bf16 conversions into K'=3072 layouts
// A-side: hi at k and k+1024, lo at k+2048
// B-side: hi at k and k+2048, lo at k+1024
// NOTE: all destination __device__ globals are referenced INSIDE the kernels
// (passing a __device__ symbol as a host-side kernel arg gives the host
// shadow address — the round-3 bug).
// ---------------------------------------------------------------------------
__device__ __forceinline__ void split4(const float4 v, __nv_bfloat162* h,
                                       __nv_bfloat162* l) {
    const __nv_bfloat16 h0 = __float2bfloat16(v.x);
    const __nv_bfloat16 h1 = __float2bfloat16(v.y);
    const __nv_bfloat16 h2 = __float2bfloat16(v.z);
    const __nv_bfloat16 h3 = __float2bfloat16(v.w);
    h[0] = __nv_bfloat162(h0, h1);
    h[1] = __nv_bfloat162(h2, h3);
    l[0] = __nv_bfloat162(__float2bfloat16(v.x - __bfloat162float(h0)),
                          __float2bfloat16(v.y - __bfloat162float(h1)));
    l[1] = __nv_bfloat162(__float2bfloat16(v.z - __bfloat162float(h2)),
                          __float2bfloat16(v.w - __bfloat162float(h3)));
}

__global__ void conv_x_kernel(const float* __restrict__ src) {
    const int i = blockIdx.x * blockDim.x + threadIdx.x;   // over M*K/4
    if (i >= M_ROWS * K_DIM / 4) return;
    const int r = i / (K_DIM / 4);
    const int k4 = (i % (K_DIM / 4)) * 4;
    float4 v = ((const float4*)src)[i];
    __nv_bfloat162 h[2], l[2];
    split4(v, h, l);
    __nv_bfloat162* d0 = (__nv_bfloat162*)(g_xs + (size_t)r * KP + k4);
    __nv_bfloat162* d1 = (__nv_bfloat162*)(g_xs + (size_t)r * KP + 1024 + k4);
    __nv_bfloat162* d2 = (__nv_bfloat162*)(g_xs + (size_t)r * KP + 2048 + k4);
    d0[0] = h[0]; d0[1] = h[1];
    d1[0] = h[0]; d1[1] = h[1];
    d2[0] = l[0]; d2[1] = l[1];
}

__global__ void conv_w_kernel(const float* __restrict__ Wq, const float* __restrict__ Wk,
                              const float* __restrict__ Wv, const float* __restrict__ Wo) {
    const int z = blockIdx.z;
    const float* src = (z == 0) ? Wq : (z == 1) ? Wk : (z == 2) ? Wv : Wo;
    const int i = blockIdx.x * blockDim.x + threadIdx.x;   // over N*K/4
    if (i >= N_DIM * K_DIM / 4) return;
    const int n = i / (K_DIM / 4);
    const int k4 = (i % (K_DIM / 4)) * 4;
    float4 v = ((const float4*)src)[i];
    __nv_bfloat162 h[2], l[2];
    split4(v, h, l);
    __nv_bfloat16* dst = g_Ws + (size_t)z * N_DIM * KP;
    __nv_bfloat162* d0 = (__nv_bfloat162*)(dst + (size_t)n * KP + k4);
    __nv_bfloat162* d1 = (__nv_bfloat162*)(dst + (size_t)n * KP + 1024 + k4);
    __nv_bfloat162* d2 = (__nv_bfloat162*)(dst + (size_t)n * KP + 2048 + k4);
    d0[0] = h[0]; d0[1] = h[1];
    d1[0] = l[0]; d1[1] = l[1];
    d2[0] = h[0]; d2[1] = h[1];
}

__global__ void conv_attnout_kernel() {
    const int i = blockIdx.x * blockDim.x + threadIdx.x;
    if (i >= M_ROWS * K_DIM / 4) return;
    const int r = i / (K_DIM / 4);
    const int k4 = (i % (K_DIM / 4)) * 4;
    float4 v = ((const float4*)g_A)[i];
    __nv_bfloat162 h[2], l[2];
    split4(v, h, l);
    __nv_bfloat162* d0 = (__nv_bfloat162*)(g_As + (size_t)r * KP + k4);
    __nv_bfloat162* d1 = (__nv_bfloat162*)(g_As + (size_t)r * KP + 1024 + k4);
    __nv_bfloat162* d2 = (__nv_bfloat162*)(g_As + (size_t)r * KP + 2048 + k4);
    d0[0] = h[0]; d0[1] = h[1];
    d1[0] = h[0]; d1[1] = h[1];
    d2[0] = l[0]; d2[1] = l[1];
}

// ---------------------------------------------------------------------------
// Attention: fp32 SIMT flash-style (validated round 1, unchanged)
// ---------------------------------------------------------------------------
#define LDK 65
#define ATTN_SMEM_BYTES ((64*64 + 64*LDK + 64*64) * 4)

__global__ __launch_bounds__(256) void attn_kernel()
{
    extern __shared__ float smf[];
    float* Qst = smf;
    float* Ks  = smf + 64 * 64;
    float* Vs  = smf + 64 * 64 + 64 * LDK;

    const int qt  = blockIdx.x;
    const int bh  = blockIdx.y;
    const int b   = bh >> 4;
    const int h   = bh & 15;
    const int tid = threadIdx.x;
    const int ty  = tid >> 4;
    const int tx  = tid & 15;

    const int qrow0 = b * TSEQ + qt * 64;
    const int cbase = h * DHEAD;

    for (int i = tid; i < 64 * 16; i += 256) {
        const int r  = i >> 4;
        const int c4 = (i & 15) << 2;
        float4 v = *(const float4*)&g_Q[(qrow0 + r) * K_DIM + cbase + c4];
        Qst[(c4 + 0) * 64 + r] = v.x;
        Qst[(c4 + 1) * 64 + r] = v.y;
        Qst[(c4 + 2) * 64 + r] = v.z;
        Qst[(c4 + 3) * 64 + r] = v.w;
    }

    float acc[4][4];
    float m_i[4], l_i[4];
#pragma unroll
    for (int i = 0; i < 4; i++) {
        m_i[i] = -INFINITY; l_i[i] = 0.f;
#pragma unroll
        for (int j = 0; j < 4; j++) acc[i][j] = 0.f;
    }

    for (int kt = 0; kt < 16; kt++) {
        __syncthreads();
        const int krow0 = b * TSEQ + kt * 64;
        for (int i = tid; i < 64 * 16; i += 256) {
            const int r  = i >> 4;
            const int c4 = (i & 15) << 2;
            float4 kv = *(const float4*)&g_K[(krow0 + r) * K_DIM + cbase + c4];
            Ks[r * LDK + c4 + 0] = kv.x;
            Ks[r * LDK + c4 + 1] = kv.y;
            Ks[r * LDK + c4 + 2] = kv.z;
            Ks[r * LDK + c4 + 3] = kv.w;
            float4 vv = *(const float4*)&g_V[(krow0 + r) * K_DIM + cbase + c4];
            *(float4*)&Vs[r * 64 + c4] = vv;
        }
        __syncthreads();

        float s[4][4];
#pragma unroll
        for (int i = 0; i < 4; i++)
#pragma unroll
            for (int j = 0; j < 4; j++) s[i][j] = 0.f;

#pragma unroll 8
        for (int kk = 0; kk < 64; kk++) {
            float qv[4];
            *(float4*)qv = *(const float4*)&Qst[kk * 64 + ty * 4];
            float bv[4];
            bv[0] = Ks[(tx * 4 + 0) * LDK + kk];
            bv[1] = Ks[(tx * 4 + 1) * LDK + kk];
            bv[2] = Ks[(tx * 4 + 2) * LDK + kk];
            bv[3] = Ks[(tx * 4 + 3) * LDK + kk];
#pragma unroll
            for (int i = 0; i < 4; i++)
#pragma unroll
                for (int j = 0; j < 4; j++)
                    s[i][j] = fmaf(qv[i], bv[j], s[i][j]);
        }

#pragma unroll
        for (int i = 0; i < 4; i++) {
            float rm = -INFINITY;
#pragma unroll
            for (int j = 0; j < 4; j++) {
                s[i][j] *= 0.125f;
                rm = fmaxf(rm, s[i][j]);
            }
#pragma unroll
            for (int off = 8; off > 0; off >>= 1)
                rm = fmaxf(rm, __shfl_xor_sync(0xffffffffu, rm, off));
            const float nm    = fmaxf(m_i[i], rm);
            const float alpha = __expf(m_i[i] - nm);
            float rs = 0.f;
#pragma unroll
            for (int j = 0; j < 4; j++) {
                s[i][j] = __expf(s[i][j] - nm);
                rs += s[i][j];
            }
#pragma unroll
            for (int off = 8; off > 0; off >>= 1)
                rs += __shfl_xor_sync(0xffffffffu, rs, off);
            l_i[i] = l_i[i] * alpha + rs;
            m_i[i] = nm;
#pragma unroll
            for (int j = 0; j < 4; j++) acc[i][j] *= alpha;
        }

        __syncthreads();
#pragma unroll
        for (int i = 0; i < 4; i++)
#pragma unroll
            for (int j = 0; j < 4; j++)
                Ks[(ty * 4 + i) * LDK + tx * 4 + j] = s[i][j];
        __syncthreads();

#pragma unroll 8
        for (int kk = 0; kk < 64; kk++) {
            float vv[4];
            *(float4*)vv = *(const float4*)&Vs[kk * 64 + tx * 4];
            float pv[4];
            pv[0] = Ks[(ty * 4 + 0) * LDK + kk];
            pv[1] = Ks[(ty * 4 + 1) * LDK + kk];
            pv[2] = Ks[(ty * 4 + 2) * LDK + kk];
            pv[3] = Ks[(ty * 4 + 3) * LDK + kk];
#pragma unroll
            for (int i = 0; i < 4; i++)
#pragma unroll
                for (int j = 0; j < 4; j++)
                    acc[i][j] = fmaf(pv[i], vv[j], acc[i][j]);
        }
    }

#pragma unroll
    for (int i = 0; i < 4; i++) {
        const float inv = 1.0f / l_i[i];
        float4 o;
        o.x = acc[i][0] * inv;
        o.y = acc[i][1] * inv;
        o.z = acc[i][2] * inv;
        o.w = acc[i][3] * inv;
        *(float4*)&g_A[(qrow0 + ty * 4 + i) * K_DIM + cbase + tx * 4] = o;
    }
}

// ---------------------------------------------------------------------------
// kernel_launch
// ---------------------------------------------------------------------------
extern "C" void kernel_launch(void* const* d_in, const int* in_sizes, int n_in,
                              void* d_out, int out_size)
{
    const float* x  = (const float*)d_in[0];
    const float* Wq = (const float*)d_in[1];
    const float* Wk = (const float*)d_in[2];
    const float* Wv = (const float*)d_in[3];
    const float* Wo = (const float*)d_in[4];
    const float* bo = (const float*)d_in[5];
    float* out = (float*)d_out;

    cudaFuncSetAttribute(qkv_hmma_kernel, cudaFuncAttributeMaxDynamicSharedMemorySize, GEMM_SMEM);
    cudaFuncSetAttribute(out_hmma_kernel, cudaFuncAttributeMaxDynamicSharedMemorySize, GEMM_SMEM);
    cudaFuncSetAttribute(attn_kernel, cudaFuncAttributeMaxDynamicSharedMemorySize, ATTN_SMEM_BYTES);

    // 1) split-precision conversions
    {
        const int nx = M_ROWS * K_DIM / 4;
        conv_x_kernel<<<(nx + 255) / 256, 256>>>(x);
        const int nw = N_DIM * K_DIM / 4;
        conv_w_kernel<<<dim3((nw + 255) / 256, 1, 4), 256>>>(Wq, Wk, Wv, Wo);
    }

    // 2) QKV projections (HMMA)
    qkv_hmma_kernel<<<dim3(N_DIM / GBN, M_ROWS / GBM, 3), 256, GEMM_SMEM>>>();

    // 3) attention (fp32 SIMT)
    attn_kernel<<<dim3(16, BATCH * HEADS), 256, ATTN_SMEM_BYTES>>>();

    // 4) convert attention output, output projection + bias (HMMA)
    {
        const int na = M_ROWS * K_DIM / 4;
        conv_attnout_kernel<<<(na + 255) / 256, 256>>>();
    }
    out_hmma_kernel<<<dim3(N_DIM / GBN, M_ROWS / GBM), 256, GEMM_SMEM>>>(bo, out);
}

// round 5
// speedup vs baseline: 1.7603x; 1.3532x over previous
#include <cuda_runtime.h>
#include <cuda_bf16.h>
#include <math.h>
#include <stdint.h>
#include <string.h>

// ---------------------------------------------------------------------------
// Problem constants
// ---------------------------------------------------------------------------
#define M_ROWS 4096
#define K_DIM  1024
#define N_DIM  1024
#define HEADS  16
#define DHEAD  64
#define TSEQ   1024
#define BATCH  4

// split-bf16 widened K for projections
#define KP     3072

// fp32 scratch
__device__ float g_Q[M_ROWS * K_DIM];
__device__ float g_K[M_ROWS * K_DIM];
__device__ float g_V[M_ROWS * K_DIM];
__device__ float g_A[M_ROWS * K_DIM];

// split-bf16 scratch for projection GEMMs
__device__ __align__(16) __nv_bfloat16 g_xs[M_ROWS * KP];
__device__ __align__(16) __nv_bfloat16 g_As[M_ROWS * KP];
__device__ __align__(16) __nv_bfloat16 g_Ws[4 * N_DIM * KP];

// attention split operands
// Q' per head: [t=1024][192]  pattern [hi|hi|lo]
// K' per head: [t=1024][192]  pattern [hi|lo|hi]
// Vt per head: [d=64][t=1024] hi and lo
__device__ __align__(16) __nv_bfloat16 g_Qs2[64 * 1024 * 192];
__device__ __align__(16) __nv_bfloat16 g_Ks2[64 * 1024 * 192];
__device__ __align__(16) __nv_bfloat16 g_Vthi[64 * 64 * 1024];
__device__ __align__(16) __nv_bfloat16 g_Vtlo[64 * 64 * 1024];

// ---------------------------------------------------------------------------
// PTX helpers (base sm_103 target: cp.async + ldmatrix + mma.sync bf16)
// ---------------------------------------------------------------------------
__device__ __forceinline__ uint32_t smem_u32(const void* p) {
    uint32_t a;
    asm("{ .reg .u64 t; cvta.to.shared.u64 t, %1; cvt.u32.u64 %0, t; }"
        : "=r"(a) : "l"(p));
    return a;
}
__device__ __forceinline__ void cp16(uint32_t s, const void* g) {
    asm volatile("cp.async.cg.shared.global [%0], [%1], 16;" :: "r"(s), "l"(g));
}
#define CP_COMMIT() asm volatile("cp.async.commit_group;" ::: "memory")
#define CP_WAIT(n)  asm volatile("cp.async.wait_group %0;" :: "n"(n) : "memory")

#define LDSM_X4(r, addr)                                                       \
    asm volatile("ldmatrix.sync.aligned.m8n8.x4.shared.b16 {%0,%1,%2,%3}, [%4];" \
                 : "=r"((r)[0]), "=r"((r)[1]), "=r"((r)[2]), "=r"((r)[3])      \
                 : "r"(addr))

__device__ __forceinline__ void mma16816(float* c, const uint32_t* a,
                                         const uint32_t* b) {
    asm volatile(
        "mma.sync.aligned.m16n8k16.row.col.f32.bf16.bf16.f32 "
        "{%0,%1,%2,%3}, {%4,%5,%6,%7}, {%8,%9}, {%0,%1,%2,%3};"
        : "+f"(c[0]), "+f"(c[1]), "+f"(c[2]), "+f"(c[3])
        : "r"(a[0]), "r"(a[1]), "r"(a[2]), "r"(a[3]), "r"(b[0]), "r"(b[1]));
}

__device__ __forceinline__ uint32_t packbf2(float x, float y) {
    __nv_bfloat162 t = __floats2bfloat162_rn(x, y);
    uint32_t u;
    memcpy(&u, &t, 4);
    return u;
}

// ---------------------------------------------------------------------------
// HMMA bf16 NT GEMM (unchanged, validated round 4)
// ---------------------------------------------------------------------------
#define GBM 128
#define GBN 128
#define GBK 64
#define LDA 72
#define STAGE_ELEMS (128 * LDA)
#define NCH (KP / GBK)
#define GEMM_SMEM (4 * STAGE_ELEMS * 2)

__device__ __forceinline__ void load_chunk(const __nv_bfloat16* __restrict__ A,
                                           const __nv_bfloat16* __restrict__ B,
                                           int bm, int bn, int k0,
                                           uint32_t sA, uint32_t sB) {
    const int tid = threadIdx.x;
#pragma unroll
    for (int i = 0; i < 4; i++) {
        const int idx = tid * 4 + i;
        const int row = idx >> 3;
        const int seg = idx & 7;
        cp16(sA + (row * LDA + seg * 8) * 2,
             A + (size_t)(bm + row) * KP + k0 + seg * 8);
        cp16(sB + (row * LDA + seg * 8) * 2,
             B + (size_t)(bn + row) * KP + k0 + seg * 8);
    }
    CP_COMMIT();
}

__device__ void gemm_hmma_body(const __nv_bfloat16* __restrict__ A,
                               const __nv_bfloat16* __restrict__ B,
                               const float* __restrict__ bias,
                               float* __restrict__ C) {
    extern __shared__ char sm[];
    const uint32_t smb = smem_u32(sm);
    const uint32_t sA0 = smb;
    const uint32_t sB0 = smb + 2 * STAGE_ELEMS * 2;

    const int tid  = threadIdx.x;
    const int wid  = tid >> 5;
    const int lane = tid & 31;
    const int wm   = wid >> 2;
    const int wn   = wid & 3;
    const int bm   = blockIdx.y * GBM;
    const int bn   = blockIdx.x * GBN;

    float acc[4][4][4];
#pragma unroll
    for (int i = 0; i < 4; i++)
#pragma unroll
        for (int j = 0; j < 4; j++)
#pragma unroll
            for (int r = 0; r < 4; r++) acc[i][j][r] = 0.f;

    load_chunk(A, B, bm, bn, 0, sA0, sB0);

    for (int c = 0; c < NCH; c++) {
        const int buf = c & 1;
        if (c + 1 < NCH) {
            load_chunk(A, B, bm, bn, (c + 1) * GBK,
                       sA0 + ((c + 1) & 1) * STAGE_ELEMS * 2,
                       sB0 + ((c + 1) & 1) * STAGE_ELEMS * 2);
            CP_WAIT(1);
        } else {
            CP_WAIT(0);
        }
        __syncthreads();

        const uint32_t aB = sA0 + buf * STAGE_ELEMS * 2;
        const uint32_t bB = sB0 + buf * STAGE_ELEMS * 2;

#pragma unroll
        for (int ks = 0; ks < 4; ks++) {
            uint32_t afr[4][4];
#pragma unroll
            for (int mi = 0; mi < 4; mi++) {
                const int row = wm * 64 + mi * 16 + (lane & 15);
                const int col = ks * 16 + (lane >> 4) * 8;
                LDSM_X4(afr[mi], aB + (row * LDA + col) * 2);
            }
            uint32_t bfr[2][4];
#pragma unroll
            for (int np = 0; np < 2; np++) {
                const int g   = lane >> 3;
                const int row = wn * 32 + np * 16 + (g >> 1) * 8 + (lane & 7);
                const int col = ks * 16 + (g & 1) * 8;
                LDSM_X4(bfr[np], bB + (row * LDA + col) * 2);
            }
#pragma unroll
            for (int mi = 0; mi < 4; mi++) {
#pragma unroll
                for (int ni = 0; ni < 4; ni++)
                    mma16816(acc[mi][ni], afr[mi], &bfr[ni >> 1][(ni & 1) * 2]);
            }
        }
        __syncthreads();
    }

#pragma unroll
    for (int mi = 0; mi < 4; mi++) {
#pragma unroll
        for (int ni = 0; ni < 4; ni++) {
            const int r0 = bm + wm * 64 + mi * 16 + (lane >> 2);
            const int c0 = bn + wn * 32 + ni * 8 + (lane & 3) * 2;
            float2 v0 = make_float2(acc[mi][ni][0], acc[mi][ni][1]);
            float2 v1 = make_float2(acc[mi][ni][2], acc[mi][ni][3]);
            if (bias) {
                const float b0 = bias[c0], b1 = bias[c0 + 1];
                v0.x += b0; v0.y += b1;
                v1.x += b0; v1.y += b1;
            }
            *(float2*)&C[(size_t)r0 * N_DIM + c0]       = v0;
            *(float2*)&C[(size_t)(r0 + 8) * N_DIM + c0] = v1;
        }
    }
}

__global__ __launch_bounds__(256) void qkv_hmma_kernel() {
    const int z = blockIdx.z;
    float* C = (z == 0) ? g_Q : (z == 1) ? g_K : g_V;
    gemm_hmma_body(g_xs, g_Ws + (size_t)z * N_DIM * KP, nullptr, C);
}

__global__ __launch_bounds__(256) void out_hmma_kernel(const float* __restrict__ bo,
                                                       float* __restrict__ out) {
    gemm_hmma_body(g_As, g_Ws + (size_t)3 * N_DIM * KP, bo, out);
}

// ---------------------------------------------------------------------------
// fp32 -> split bf16 conversions (projection operands)
// ---------------------------------------------------------------------------
__device__ __forceinline__ void split4(const float4 v, __nv_bfloat162* h,
                                       __nv_bfloat162* l) {
    const __nv_bfloat16 h0 = __float2bfloat16(v.x);
    const __nv_bfloat16 h1 = __float2bfloat16(v.y);
    const __nv_bfloat16 h2 = __float2bfloat16(v.z);
    const __nv_bfloat16 h3 = __float2bfloat16(v.w);
    h[0] = __nv_bfloat162(h0, h1);
    h[1] = __nv_bfloat162(h2, h3);
    l[0] = __nv_bfloat162(__float2bfloat16(v.x - __bfloat162float(h0)),
                          __float2bfloat16(v.y - __bfloat162float(h1)));
    l[1] = __nv_bfloat162(__float2bfloat16(v.z - __bfloat162float(h2)),
                          __float2bfloat16(v.w - __bfloat162float(h3)));
}

__global__ void conv_x_kernel(const float* __restrict__ src) {
    const int i = blockIdx.x * blockDim.x + threadIdx.x;
    if (i >= M_ROWS * K_DIM / 4) return;
    const int r = i / (K_DIM / 4);
    const int k4 = (i % (K_DIM / 4)) * 4;
    float4 v = ((const float4*)src)[i];
    __nv_bfloat162 h[2], l[2];
    split4(v, h, l);
    __nv_bfloat162* d0 = (__nv_bfloat162*)(g_xs + (size_t)r * KP + k4);
    __nv_bfloat162* d1 = (__nv_bfloat162*)(g_xs + (size_t)r * KP + 1024 + k4);
    __nv_bfloat162* d2 = (__nv_bfloat162*)(g_xs + (size_t)r * KP + 2048 + k4);
    d0[0] = h[0]; d0[1] = h[1];
    d1[0] = h[0]; d1[1] = h[1];
    d2[0] = l[0]; d2[1] = l[1];
}

__global__ void conv_w_kernel(const float* __restrict__ Wq, const float* __restrict__ Wk,
                              const float* __restrict__ Wv, const float* __restrict__ Wo) {
    const int z = blockIdx.z;
    const float* src = (z == 0) ? Wq : (z == 1) ? Wk : (z == 2) ? Wv : Wo;
    const int i = blockIdx.x * blockDim.x + threadIdx.x;
    if (i >= N_DIM * K_DIM / 4) return;
    const int n = i / (K_DIM / 4);
    const int k4 = (i % (K_DIM / 4)) * 4;
    float4 v = ((const float4*)src)[i];
    __nv_bfloat162 h[2], l[2];
    split4(v, h, l);
    __nv_bfloat16* dst = g_Ws + (size_t)z * N_DIM * KP;
    __nv_bfloat162* d0 = (__nv_bfloat162*)(dst + (size_t)n * KP + k4);
    __nv_bfloat162* d1 = (__nv_bfloat162*)(dst + (size_t)n * KP + 1024 + k4);
    __nv_bfloat162* d2 = (__nv_bfloat162*)(dst + (size_t)n * KP + 2048 + k4);
    d0[0] = h[0]; d0[1] = h[1];
    d1[0] = l[0]; d1[1] = l[1];
    d2[0] = h[0]; d2[1] = h[1];
}

__global__ void conv_attnout_kernel() {
    const int i = blockIdx.x * blockDim.x + threadIdx.x;
    if (i >= M_ROWS * K_DIM / 4) return;
    const int r = i / (K_DIM / 4);
    const int k4 = (i % (K_DIM / 4)) * 4;
    float4 v = ((const float4*)g_A)[i];
    __nv_bfloat162 h[2], l[2];
    split4(v, h, l);
    __nv_bfloat162* d0 = (__nv_bfloat162*)(g_As + (size_t)r * KP + k4);
    __nv_bfloat162* d1 = (__nv_bfloat162*)(g_As + (size_t)r * KP + 1024 + k4);
    __nv_bfloat162* d2 = (__nv_bfloat162*)(g_As + (size_t)r * KP + 2048 + k4);
    d0[0] = h[0]; d0[1] = h[1];
    d1[0] = h[0]; d1[1] = h[1];
    d2[0] = l[0]; d2[1] = l[1];
}

// ---------------------------------------------------------------------------
// conversions for attention operands
// Q'[bh][t][192] = [hi|hi|lo],  K'[bh][t][192] = [hi|lo|hi]
// ---------------------------------------------------------------------------
__global__ void conv_qk_kernel() {
    const int i = blockIdx.x * blockDim.x + threadIdx.x;   // over 4096*256
    if (i >= M_ROWS * 256) return;
    const int row = i >> 8;           // 0..4095
    const int e4  = i & 255;          // float4 within row
    const int h   = e4 >> 4;
    const int dd  = (e4 & 15) * 4;
    const int b   = row >> 10, t = row & 1023;
    const size_t base = ((size_t)((b * 16 + h) * 1024) + t) * 192;

    float4 q = *(const float4*)&g_Q[(size_t)row * K_DIM + h * 64 + dd];
    float4 k = *(const float4*)&g_K[(size_t)row * K_DIM + h * 64 + dd];
    __nv_bfloat162 qh[2], ql[2], kh[2], kl[2];
    split4(q, qh, ql);
    split4(k, kh, kl);

    __nv_bfloat162* p;
    p = (__nv_bfloat162*)(g_Qs2 + base + dd);        p[0] = qh[0]; p[1] = qh[1];
    p = (__nv_bfloat162*)(g_Qs2 + base + 64 + dd);   p[0] = qh[0]; p[1] = qh[1];
    p = (__nv_bfloat162*)(g_Qs2 + base + 128 + dd);  p[0] = ql[0]; p[1] = ql[1];

    p = (__nv_bfloat162*)(g_Ks2 + base + dd);        p[0] = kh[0]; p[1] = kh[1];
    p = (__nv_bfloat162*)(g_Ks2 + base + 64 + dd);   p[0] = kl[0]; p[1] = kl[1];
    p = (__nv_bfloat162*)(g_Ks2 + base + 128 + dd);  p[0] = kh[0]; p[1] = kh[1];
}

// Vt[bh][d][t] hi/lo — transposed per head via smem tile
__global__ void conv_vt_kernel() {
    __shared__ float vs[64][68];
    const int blk = blockIdx.x;        // bh*16 + tt
    const int bh = blk >> 4, tt = blk & 15;
    const int b = bh >> 4, h = bh & 15;
    const int t0 = tt * 64;
    const int tid = threadIdx.x;

    const int r  = tid >> 4;           // 0..15
    const int c4 = (tid & 15) * 4;
#pragma unroll
    for (int j = 0; j < 4; j++) {
        const int t = r + j * 16;
        float4 v = *(const float4*)&g_V[(size_t)(b * 1024 + t0 + t) * K_DIM + h * 64 + c4];
        vs[t][c4 + 0] = v.x; vs[t][c4 + 1] = v.y;
        vs[t][c4 + 2] = v.z; vs[t][c4 + 3] = v.w;
    }
    __syncthreads();

    const int d  = tid >> 2;
    const int ts = (tid & 3) * 16;
    const size_t obase = ((size_t)bh * 64 + d) * 1024 + t0 + ts;
#pragma unroll
    for (int j = 0; j < 16; j += 2) {
        const float v0 = vs[ts + j][d];
        const float v1 = vs[ts + j + 1][d];
        const __nv_bfloat16 h0 = __float2bfloat16(v0);
        const __nv_bfloat16 h1 = __float2bfloat16(v1);
        *(__nv_bfloat162*)&g_Vthi[obase + j] = __nv_bfloat162(h0, h1);
        *(__nv_bfloat162*)&g_Vtlo[obase + j] =
            __nv_bfloat162(__float2bfloat16(v0 - __bfloat162float(h0)),
                           __float2bfloat16(v1 - __bfloat162float(h1)));
    }
}

// ---------------------------------------------------------------------------
// HMMA flash attention
// CTA = (qtile of 128, head). 8 warps, each owns 16 query rows x full 128 keys.
// S = Q'K'^T (split, K'=192), softmax in registers, P split in registers,
// O += Phi*Vhi + Phi*Vlo + Plo*Vhi (Vt tiles in smem).
// ---------------------------------------------------------------------------
#define QLD 200    // Q'/K' smem row pitch (bf16)
#define VLD 136    // Vt smem row pitch (bf16)
#define ATTN_SMEM (2 * 128 * QLD * 2 + 2 * 64 * VLD * 2)   // 137216

__global__ __launch_bounds__(256) void attn_hmma_kernel()
{
    extern __shared__ char sm[];
    const uint32_t smb = smem_u32(sm);
    const uint32_t sQ  = smb;
    const uint32_t sK  = smb + 128 * QLD * 2;
    const uint32_t sVh = smb + 2 * 128 * QLD * 2;
    const uint32_t sVl = sVh + 64 * VLD * 2;

    const int tid  = threadIdx.x;
    const int wid  = tid >> 5;
    const int lane = tid & 31;
    const int g    = lane >> 2;
    const int qt   = blockIdx.x;          // 0..7
    const int bh   = blockIdx.y;          // 0..63
    const int b    = bh >> 4;
    const int h    = bh & 15;
    const int cbase = h * DHEAD;
    const int qrow0 = b * TSEQ + qt * 128;

    // load Q' tile (128 x 192) once
    for (int i = tid; i < 128 * 24; i += 256) {
        const int r = i / 24, s = i % 24;
        cp16(sQ + (r * QLD + s * 8) * 2,
             g_Qs2 + ((size_t)bh * 1024 + qt * 128 + r) * 192 + s * 8);
    }
    CP_COMMIT();

    float acc_o[8][4];
#pragma unroll
    for (int i = 0; i < 8; i++)
#pragma unroll
        for (int r = 0; r < 4; r++) acc_o[i][r] = 0.f;
    float m0 = -INFINITY, m1 = -INFINITY, l0 = 0.f, l1 = 0.f;

    for (int kt = 0; kt < 8; kt++) {
        __syncthreads();   // previous iteration done reading K/V smem
        for (int i = tid; i < 128 * 24; i += 256) {
            const int r = i / 24, s = i % 24;
            cp16(sK + (r * QLD + s * 8) * 2,
                 g_Ks2 + ((size_t)bh * 1024 + kt * 128 + r) * 192 + s * 8);
        }
        for (int i = tid; i < 64 * 16; i += 256) {
            const int r = i / 16, s = i % 16;
            cp16(sVh + (r * VLD + s * 8) * 2,
                 g_Vthi + ((size_t)bh * 64 + r) * 1024 + kt * 128 + s * 8);
            cp16(sVl + (r * VLD + s * 8) * 2,
                 g_Vtlo + ((size_t)bh * 64 + r) * 1024 + kt * 128 + s * 8);
        }
        CP_COMMIT();
        CP_WAIT(0);
        __syncthreads();

        // ---- S = Q' K'^T : warp rows wid*16..+15, keys 0..127 ----
        float s_acc[16][4];
#pragma unroll
        for (int ni = 0; ni < 16; ni++)
#pragma unroll
            for (int r = 0; r < 4; r++) s_acc[ni][r] = 0.f;

#pragma unroll
        for (int ks = 0; ks < 12; ks++) {
            uint32_t a[4];
            LDSM_X4(a, sQ + ((wid * 16 + (lane & 15)) * QLD + ks * 16 + (lane >> 4) * 8) * 2);
            uint32_t bf[8][4];
            const int gg = lane >> 3;
#pragma unroll
            for (int np = 0; np < 8; np++) {
                const int row = np * 16 + (gg >> 1) * 8 + (lane & 7);
                LDSM_X4(bf[np], sK + (row * QLD + ks * 16 + (gg & 1) * 8) * 2);
            }
#pragma unroll
            for (int ni = 0; ni < 16; ni++)
                mma16816(s_acc[ni], a, &bf[ni >> 1][(ni & 1) * 2]);
        }

        // ---- online softmax (rows g and g+8 of warp block) ----
        float rm0 = -INFINITY, rm1 = -INFINITY;
#pragma unroll
        for (int ni = 0; ni < 16; ni++) {
            s_acc[ni][0] *= 0.125f; s_acc[ni][1] *= 0.125f;
            s_acc[ni][2] *= 0.125f; s_acc[ni][3] *= 0.125f;
            rm0 = fmaxf(rm0, fmaxf(s_acc[ni][0], s_acc[ni][1]));
            rm1 = fmaxf(rm1, fmaxf(s_acc[ni][2], s_acc[ni][3]));
        }
        rm0 = fmaxf(rm0, __shfl_xor_sync(0xffffffffu, rm0, 1));
        rm0 = fmaxf(rm0, __shfl_xor_sync(0xffffffffu, rm0, 2));
        rm1 = fmaxf(rm1, __shfl_xor_sync(0xffffffffu, rm1, 1));
        rm1 = fmaxf(rm1, __shfl_xor_sync(0xffffffffu, rm1, 2));

        const float nm0 = fmaxf(m0, rm0);
        const float nm1 = fmaxf(m1, rm1);
        const float a0 = __expf(m0 - nm0);
        const float a1 = __expf(m1 - nm1);

        float rs0 = 0.f, rs1 = 0.f;
#pragma unroll
        for (int ni = 0; ni < 16; ni++) {
            s_acc[ni][0] = __expf(s_acc[ni][0] - nm0);
            s_acc[ni][1] = __expf(s_acc[ni][1] - nm0);
            s_acc[ni][2] = __expf(s_acc[ni][2] - nm1);
            s_acc[ni][3] = __expf(s_acc[ni][3] - nm1);
            rs0 += s_acc[ni][0] + s_acc[ni][1];
            rs1 += s_acc[ni][2] + s_acc[ni][3];
        }
        rs0 += __shfl_xor_sync(0xffffffffu, rs0, 1);
        rs0 += __shfl_xor_sync(0xffffffffu, rs0, 2);
        rs1 += __shfl_xor_sync(0xffffffffu, rs1, 1);
        rs1 += __shfl_xor_sync(0xffffffffu, rs1, 2);

        l0 = l0 * a0 + rs0;  m0 = nm0;
        l1 = l1 * a1 + rs1;  m1 = nm1;

#pragma unroll
        for (int ni = 0; ni < 8; ni++) {
            acc_o[ni][0] *= a0; acc_o[ni][1] *= a0;
            acc_o[ni][2] *= a1; acc_o[ni][3] *= a1;
        }

        // ---- O += P V : P from registers (FA2 fragment reuse), split ----
        const int gg = lane >> 3;
#pragma unroll
        for (int ks = 0; ks < 8; ks++) {
            // pack Phi / Plo A-fragments from S tiles 2ks, 2ks+1
            uint32_t ph[4], pl[4];
            {
                const float* t0 = s_acc[2 * ks];
                const float* t1 = s_acc[2 * ks + 1];
                ph[0] = packbf2(t0[0], t0[1]);
                ph[1] = packbf2(t0[2], t0[3]);
                ph[2] = packbf2(t1[0], t1[1]);
                ph[3] = packbf2(t1[2], t1[3]);
                __nv_bfloat162 hb;
                memcpy(&hb, &ph[0], 4);
                pl[0] = packbf2(t0[0] - __bfloat162float(hb.x), t0[1] - __bfloat162float(hb.y));
                memcpy(&hb, &ph[1], 4);
                pl[1] = packbf2(t0[2] - __bfloat162float(hb.x), t0[3] - __bfloat162float(hb.y));
                memcpy(&hb, &ph[2], 4);
                pl[2] = packbf2(t1[0] - __bfloat162float(hb.x), t1[1] - __bfloat162float(hb.y));
                memcpy(&hb, &ph[3], 4);
                pl[3] = packbf2(t1[2] - __bfloat162float(hb.x), t1[3] - __bfloat162float(hb.y));
            }
            uint32_t vh[4][4], vl[4][4];
#pragma unroll
            for (int np = 0; np < 4; np++) {
                const int row = np * 16 + (gg >> 1) * 8 + (lane & 7);
                const int col = ks * 16 + (gg & 1) * 8;
                LDSM_X4(vh[np], sVh + (row * VLD + col) * 2);
                LDSM_X4(vl[np], sVl + (row * VLD + col) * 2);
            }
#pragma unroll
            for (int ni = 0; ni < 8; ni++) {
                mma16816(acc_o[ni], ph, &vh[ni >> 1][(ni & 1) * 2]);
                mma16816(acc_o[ni], ph, &vl[ni >> 1][(ni & 1) * 2]);
                mma16816(acc_o[ni], pl, &vh[ni >> 1][(ni & 1) * 2]);
            }
        }
    }

    // ---- normalize and write g_A ----
    const float inv0 = 1.0f / l0;
    const float inv1 = 1.0f / l1;
    const int row0 = qrow0 + wid * 16 + g;
#pragma unroll
    for (int ni = 0; ni < 8; ni++) {
        const int col = cbase + ni * 8 + (lane & 3) * 2;
        *(float2*)&g_A[(size_t)row0 * K_DIM + col] =
            make_float2(acc_o[ni][0] * inv0, acc_o[ni][1] * inv0);
        *(float2*)&g_A[(size_t)(row0 + 8) * K_DIM + col] =
            make_float2(acc_o[ni][2] * inv1, acc_o[ni][3] * inv1);
    }
}

// ---------------------------------------------------------------------------
// kernel_launch
// ---------------------------------------------------------------------------
extern "C" void kernel_launch(void* const* d_in, const int* in_sizes, int n_in,
                              void* d_out, int out_size)
{
    const float* x  = (const float*)d_in[0];
    const float* Wq = (const float*)d_in[1];
    const float* Wk = (const float*)d_in[2];
    const float* Wv = (const float*)d_in[3];
    const float* Wo = (const float*)d_in[4];
    const float* bo = (const float*)d_in[5];
    float* out = (float*)d_out;

    cudaFuncSetAttribute(qkv_hmma_kernel, cudaFuncAttributeMaxDynamicSharedMemorySize, GEMM_SMEM);
    cudaFuncSetAttribute(out_hmma_kernel, cudaFuncAttributeMaxDynamicSharedMemorySize, GEMM_SMEM);
    cudaFuncSetAttribute(attn_hmma_kernel, cudaFuncAttributeMaxDynamicSharedMemorySize, ATTN_SMEM);

    // 1) split conversions for projections
    {
        const int nx = M_ROWS * K_DIM / 4;
        conv_x_kernel<<<(nx + 255) / 256, 256>>>(x);
        const int nw = N_DIM * K_DIM / 4;
        conv_w_kernel<<<dim3((nw + 255) / 256, 1, 4), 256>>>(Wq, Wk, Wv, Wo);
    }

    // 2) QKV projections (HMMA)
    qkv_hmma_kernel<<<dim3(N_DIM / GBN, M_ROWS / GBM, 3), 256, GEMM_SMEM>>>();

    // 3) attention operand conversions
    conv_qk_kernel<<<(M_ROWS * 256) / 256, 256>>>();
    conv_vt_kernel<<<64 * 16, 256>>>();

    // 4) attention (HMMA flash, split precision)
    attn_hmma_kernel<<<dim3(8, 64), 256, ATTN_SMEM>>>();

    // 5) output projection
    {
        const int na = M_ROWS * K_DIM / 4;
        conv_attnout_kernel<<<(na + 255) / 256, 256>>>();
    }
    out_hmma_kernel<<<dim3(N_DIM / GBN, M_ROWS / GBM), 256, GEMM_SMEM>>>(bo, out);
}

// round 6
// speedup vs baseline: 2.0520x; 1.1657x over previous
#include <cuda_runtime.h>
#include <cuda_bf16.h>
#include <math.h>
#include <stdint.h>
#include <string.h>

// ---------------------------------------------------------------------------
// Problem constants
// ---------------------------------------------------------------------------
#define M_ROWS 4096
#define K_DIM  1024
#define N_DIM  1024
#define HEADS  16
#define DHEAD  64
#define TSEQ   1024
#define BATCH  4

// split-bf16 widened K for projections
#define KP     3072

// fp32 scratch (attention inputs only; attention output goes straight to g_As)
__device__ float g_Q[M_ROWS * K_DIM];
__device__ float g_K[M_ROWS * K_DIM];
__device__ float g_V[M_ROWS * K_DIM];

// split-bf16 scratch for projection GEMMs
__device__ __align__(16) __nv_bfloat16 g_xs[M_ROWS * KP];
__device__ __align__(16) __nv_bfloat16 g_As[M_ROWS * KP];
__device__ __align__(16) __nv_bfloat16 g_Ws[4 * N_DIM * KP];

// attention split operands
__device__ __align__(16) __nv_bfloat16 g_Qs2[64 * 1024 * 192];
__device__ __align__(16) __nv_bfloat16 g_Ks2[64 * 1024 * 192];
__device__ __align__(16) __nv_bfloat16 g_Vthi[64 * 64 * 1024];
__device__ __align__(16) __nv_bfloat16 g_Vtlo[64 * 64 * 1024];

// ---------------------------------------------------------------------------
// PTX helpers
// ---------------------------------------------------------------------------
__device__ __forceinline__ uint32_t smem_u32(const void* p) {
    uint32_t a;
    asm("{ .reg .u64 t; cvta.to.shared.u64 t, %1; cvt.u32.u64 %0, t; }"
        : "=r"(a) : "l"(p));
    return a;
}
__device__ __forceinline__ void cp16(uint32_t s, const void* g) {
    asm volatile("cp.async.cg.shared.global [%0], [%1], 16;" :: "r"(s), "l"(g));
}
#define CP_COMMIT() asm volatile("cp.async.commit_group;" ::: "memory")
#define CP_WAIT(n)  asm volatile("cp.async.wait_group %0;" :: "n"(n) : "memory")

#define LDSM_X4(r, addr)                                                       \
    asm volatile("ldmatrix.sync.aligned.m8n8.x4.shared.b16 {%0,%1,%2,%3}, [%4];" \
                 : "=r"((r)[0]), "=r"((r)[1]), "=r"((r)[2]), "=r"((r)[3])      \
                 : "r"(addr))

__device__ __forceinline__ void mma16816(float* c, const uint32_t* a,
                                         const uint32_t* b) {
    asm volatile(
        "mma.sync.aligned.m16n8k16.row.col.f32.bf16.bf16.f32 "
        "{%0,%1,%2,%3}, {%4,%5,%6,%7}, {%8,%9}, {%0,%1,%2,%3};"
        : "+f"(c[0]), "+f"(c[1]), "+f"(c[2]), "+f"(c[3])
        : "r"(a[0]), "r"(a[1]), "r"(a[2]), "r"(a[3]), "r"(b[0]), "r"(b[1]));
}

__device__ __forceinline__ uint32_t packbf2(float x, float y) {
    __nv_bfloat162 t = __floats2bfloat162_rn(x, y);
    uint32_t u;
    memcpy(&u, &t, 4);
    return u;
}

// ---------------------------------------------------------------------------
// HMMA bf16 NT GEMM v2: swizzled smem, 3-stage cp.async pipeline, 2 CTAs/SM.
// C[M,N] = A'[M,KP] @ B'[N,KP]^T (+ bias).  CTA 128x128, BK=64, 256 thr.
// Smem tile: 128 rows x 128B; byte addr = row*128 + (seg ^ (row&7))*16.
// ---------------------------------------------------------------------------
#define GBM 128
#define GBN 128
#define GBK 64
#define TILE_B  (128 * 128)
#define STAGE_B (2 * TILE_B)
#define NSTAGE  3
#define NCH     (KP / GBK)               // 48
#define GEMM_SMEM (NSTAGE * STAGE_B)     // 98304

__device__ __forceinline__ uint32_t swz(uint32_t row, uint32_t seg) {
    return row * 128 + ((seg ^ (row & 7)) * 16);
}

__device__ __forceinline__ void load_chunk(const __nv_bfloat16* __restrict__ A,
                                           const __nv_bfloat16* __restrict__ B,
                                           int bm, int bn, int k0,
                                           uint32_t sA, uint32_t sB) {
    const int tid = threadIdx.x;
    const int row = tid >> 1;            // 0..127
    const int sb  = (tid & 1) * 4;       // 0 or 4
#pragma unroll
    for (int j = 0; j < 4; j++) {
        const int seg = sb + j;
        cp16(sA + swz(row, seg), A + (size_t)(bm + row) * KP + k0 + seg * 8);
        cp16(sB + swz(row, seg), B + (size_t)(bn + row) * KP + k0 + seg * 8);
    }
    CP_COMMIT();
}

__device__ void gemm_hmma_body(const __nv_bfloat16* __restrict__ A,
                               const __nv_bfloat16* __restrict__ B,
                               const float* __restrict__ bias,
                               float* __restrict__ C) {
    extern __shared__ char sm[];
    const uint32_t smb = smem_u32(sm);

    const int tid  = threadIdx.x;
    const int wid  = tid >> 5;
    const int lane = tid & 31;
    const int wm   = wid >> 2;
    const int wn   = wid & 3;
    const int bm   = blockIdx.y * GBM;
    const int bn   = blockIdx.x * GBN;

    float acc[4][4][4];
#pragma unroll
    for (int i = 0; i < 4; i++)
#pragma unroll
        for (int j = 0; j < 4; j++)
#pragma unroll
            for (int r = 0; r < 4; r++) acc[i][j][r] = 0.f;

    // prologue: fill 3 stages
#pragma unroll
    for (int s = 0; s < NSTAGE; s++)
        load_chunk(A, B, bm, bn, s * GBK,
                   smb + s * STAGE_B, smb + s * STAGE_B + TILE_B);

    for (int c = 0; c < NCH; c++) {
        const int rem = NCH - 1 - c;     // groups issued after group c
        if (rem >= 2)      CP_WAIT(2);
        else if (rem == 1) CP_WAIT(1);
        else               CP_WAIT(0);
        __syncthreads();

        const uint32_t aB = smb + (c % NSTAGE) * STAGE_B;
        const uint32_t bB = aB + TILE_B;

#pragma unroll
        for (int ks = 0; ks < 4; ks++) {
            uint32_t afr[4][4];
#pragma unroll
            for (int mi = 0; mi < 4; mi++) {
                const int row = wm * 64 + mi * 16 + (lane & 15);
                const int seg = ks * 2 + (lane >> 4);
                LDSM_X4(afr[mi], aB + swz(row, seg));
            }
            uint32_t bfr[2][4];
            const int g = lane >> 3;
#pragma unroll
            for (int np = 0; np < 2; np++) {
                const int row = wn * 32 + np * 16 + (g >> 1) * 8 + (lane & 7);
                const int seg = ks * 2 + (g & 1);
                LDSM_X4(bfr[np], bB + swz(row, seg));
            }
#pragma unroll
            for (int mi = 0; mi < 4; mi++) {
#pragma unroll
                for (int ni = 0; ni < 4; ni++)
                    mma16816(acc[mi][ni], afr[mi], &bfr[ni >> 1][(ni & 1) * 2]);
            }
        }
        __syncthreads();

        if (c + NSTAGE < NCH)
            load_chunk(A, B, bm, bn, (c + NSTAGE) * GBK,
                       smb + (c % NSTAGE) * STAGE_B,
                       smb + (c % NSTAGE) * STAGE_B + TILE_B);
    }

    // epilogue: direct float2 stores
#pragma unroll
    for (int mi = 0; mi < 4; mi++) {
#pragma unroll
        for (int ni = 0; ni < 4; ni++) {
            const int r0 = bm + wm * 64 + mi * 16 + (lane >> 2);
            const int c0 = bn + wn * 32 + ni * 8 + (lane & 3) * 2;
            float2 v0 = make_float2(acc[mi][ni][0], acc[mi][ni][1]);
            float2 v1 = make_float2(acc[mi][ni][2], acc[mi][ni][3]);
            if (bias) {
                const float b0 = bias[c0], b1 = bias[c0 + 1];
                v0.x += b0; v0.y += b1;
                v1.x += b0; v1.y += b1;
            }
            *(float2*)&C[(size_t)r0 * N_DIM + c0]       = v0;
            *(float2*)&C[(size_t)(r0 + 8) * N_DIM + c0] = v1;
        }
    }
}

__global__ __launch_bounds__(256, 2) void qkv_hmma_kernel() {
    const int z = blockIdx.z;
    float* C = (z == 0) ? g_Q : (z == 1) ? g_K : g_V;
    gemm_hmma_body(g_xs, g_Ws + (size_t)z * N_DIM * KP, nullptr, C);
}

__global__ __launch_bounds__(256, 2) void out_hmma_kernel(const float* __restrict__ bo,
                                                          float* __restrict__ out) {
    gemm_hmma_body(g_As, g_Ws + (size_t)3 * N_DIM * KP, bo, out);
}

// ---------------------------------------------------------------------------
// fp32 -> split bf16 conversions
// ---------------------------------------------------------------------------
__device__ __forceinline__ void split4(const float4 v, __nv_bfloat162* h,
                                       __nv_bfloat162* l) {
    const __nv_bfloat16 h0 = __float2bfloat16(v.x);
    const __nv_bfloat16 h1 = __float2bfloat16(v.y);
    const __nv_bfloat16 h2 = __float2bfloat16(v.z);
    const __nv_bfloat16 h3 = __float2bfloat16(v.w);
    h[0] = __nv_bfloat162(h0, h1);
    h[1] = __nv_bfloat162(h2, h3);
    l[0] = __nv_bfloat162(__float2bfloat16(v.x - __bfloat162float(h0)),
                          __float2bfloat16(v.y - __bfloat162float(h1)));
    l[1] = __nv_bfloat162(__float2bfloat16(v.z - __bfloat162float(h2)),
                          __float2bfloat16(v.w - __bfloat162float(h3)));
}

__global__ void conv_x_kernel(const float* __restrict__ src) {
    const int i = blockIdx.x * blockDim.x + threadIdx.x;
    if (i >= M_ROWS * K_DIM / 4) return;
    const int r = i / (K_DIM / 4);
    const int k4 = (i % (K_DIM / 4)) * 4;
    float4 v = ((const float4*)src)[i];
    __nv_bfloat162 h[2], l[2];
    split4(v, h, l);
    __nv_bfloat162* d0 = (__nv_bfloat162*)(g_xs + (size_t)r * KP + k4);
    __nv_bfloat162* d1 = (__nv_bfloat162*)(g_xs + (size_t)r * KP + 1024 + k4);
    __nv_bfloat162* d2 = (__nv_bfloat162*)(g_xs + (size_t)r * KP + 2048 + k4);
    d0[0] = h[0]; d0[1] = h[1];
    d1[0] = h[0]; d1[1] = h[1];
    d2[0] = l[0]; d2[1] = l[1];
}

__global__ void conv_w_kernel(const float* __restrict__ Wq, const float* __restrict__ Wk,
                              const float* __restrict__ Wv, const float* __restrict__ Wo) {
    const int z = blockIdx.z;
    const float* src = (z == 0) ? Wq : (z == 1) ? Wk : (z == 2) ? Wv : Wo;
    const int i = blockIdx.x * blockDim.x + threadIdx.x;
    if (i >= N_DIM * K_DIM / 4) return;
    const int n = i / (K_DIM / 4);
    const int k4 = (i % (K_DIM / 4)) * 4;
    float4 v = ((const float4*)src)[i];
    __nv_bfloat162 h[2], l[2];
    split4(v, h, l);
    __nv_bfloat16* dst = g_Ws + (size_t)z * N_DIM * KP;
    __nv_bfloat162* d0 = (__nv_bfloat162*)(dst + (size_t)n * KP + k4);
    __nv_bfloat162* d1 = (__nv_bfloat162*)(dst + (size_t)n * KP + 1024 + k4);
    __nv_bfloat162* d2 = (__nv_bfloat162*)(dst + (size_t)n * KP + 2048 + k4);
    d0[0] = h[0]; d0[1] = h[1];
    d1[0] = l[0]; d1[1] = l[1];
    d2[0] = h[0]; d2[1] = h[1];
}

// Q'[bh][t][192] = [hi|hi|lo],  K'[bh][t][192] = [hi|lo|hi]
__global__ void conv_qk_kernel() {
    const int i = blockIdx.x * blockDim.x + threadIdx.x;
    if (i >= M_ROWS * 256) return;
    const int row = i >> 8;
    const int e4  = i & 255;
    const int h   = e4 >> 4;
    const int dd  = (e4 & 15) * 4;
    const int b   = row >> 10, t = row & 1023;
    const size_t base = ((size_t)((b * 16 + h) * 1024) + t) * 192;

    float4 q = *(const float4*)&g_Q[(size_t)row * K_DIM + h * 64 + dd];
    float4 k = *(const float4*)&g_K[(size_t)row * K_DIM + h * 64 + dd];
    __nv_bfloat162 qh[2], ql[2], kh[2], kl[2];
    split4(q, qh, ql);
    split4(k, kh, kl);

    __nv_bfloat162* p;
    p = (__nv_bfloat162*)(g_Qs2 + base + dd);        p[0] = qh[0]; p[1] = qh[1];
    p = (__nv_bfloat162*)(g_Qs2 + base + 64 + dd);   p[0] = qh[0]; p[1] = qh[1];
    p = (__nv_bfloat162*)(g_Qs2 + base + 128 + dd);  p[0] = ql[0]; p[1] = ql[1];

    p = (__nv_bfloat162*)(g_Ks2 + base + dd);        p[0] = kh[0]; p[1] = kh[1];
    p = (__nv_bfloat162*)(g_Ks2 + base + 64 + dd);   p[0] = kl[0]; p[1] = kl[1];
    p = (__nv_bfloat162*)(g_Ks2 + base + 128 + dd);  p[0] = kh[0]; p[1] = kh[1];
}

// Vt[bh][d][t] hi/lo — transposed per head via smem tile
__global__ void conv_vt_kernel() {
    __shared__ float vs[64][68];
    const int blk = blockIdx.x;
    const int bh = blk >> 4, tt = blk & 15;
    const int b = bh >> 4, h = bh & 15;
    const int t0 = tt * 64;
    const int tid = threadIdx.x;

    const int r  = tid >> 4;
    const int c4 = (tid & 15) * 4;
#pragma unroll
    for (int j = 0; j < 4; j++) {
        const int t = r + j * 16;
        float4 v = *(const float4*)&g_V[(size_t)(b * 1024 + t0 + t) * K_DIM + h * 64 + c4];
        vs[t][c4 + 0] = v.x; vs[t][c4 + 1] = v.y;
        vs[t][c4 + 2] = v.z; vs[t][c4 + 3] = v.w;
    }
    __syncthreads();

    const int d  = tid >> 2;
    const int ts = (tid & 3) * 16;
    const size_t obase = ((size_t)bh * 64 + d) * 1024 + t0 + ts;
#pragma unroll
    for (int j = 0; j < 16; j += 2) {
        const float v0 = vs[ts + j][d];
        const float v1 = vs[ts + j + 1][d];
        const __nv_bfloat16 h0 = __float2bfloat16(v0);
        const __nv_bfloat16 h1 = __float2bfloat16(v1);
        *(__nv_bfloat162*)&g_Vthi[obase + j] = __nv_bfloat162(h0, h1);
        *(__nv_bfloat162*)&g_Vtlo[obase + j] =
            __nv_bfloat162(__float2bfloat16(v0 - __bfloat162float(h0)),
                           __float2bfloat16(v1 - __bfloat162float(h1)));
    }
}

// ---------------------------------------------------------------------------
// HMMA flash attention (round-5 validated) — epilogue now writes split g_As
// ---------------------------------------------------------------------------
#define QLD 200
#define VLD 136
#define ATTN_SMEM (2 * 128 * QLD * 2 + 2 * 64 * VLD * 2)

__global__ __launch_bounds__(256) void attn_hmma_kernel()
{
    extern __shared__ char sm[];
    const uint32_t smb = smem_u32(sm);
    const uint32_t sQ  = smb;
    const uint32_t sK  = smb + 128 * QLD * 2;
    const uint32_t sVh = smb + 2 * 128 * QLD * 2;
    const uint32_t sVl = sVh + 64 * VLD * 2;

    const int tid  = threadIdx.x;
    const int wid  = tid >> 5;
    const int lane = tid & 31;
    const int g    = lane >> 2;
    const int qt   = blockIdx.x;
    const int bh   = blockIdx.y;
    const int b    = bh >> 4;
    const int h    = bh & 15;
    const int cbase = h * DHEAD;
    const int qrow0 = b * TSEQ + qt * 128;

    for (int i = tid; i < 128 * 24; i += 256) {
        const int r = i / 24, s = i % 24;
        cp16(sQ + (r * QLD + s * 8) * 2,
             g_Qs2 + ((size_t)bh * 1024 + qt * 128 + r) * 192 + s * 8);
    }
    CP_COMMIT();

    float acc_o[8][4];
#pragma unroll
    for (int i = 0; i < 8; i++)
#pragma unroll
        for (int r = 0; r < 4; r++) acc_o[i][r] = 0.f;
    float m0 = -INFINITY, m1 = -INFINITY, l0 = 0.f, l1 = 0.f;

    for (int kt = 0; kt < 8; kt++) {
        __syncthreads();
        for (int i = tid; i < 128 * 24; i += 256) {
            const int r = i / 24, s = i % 24;
            cp16(sK + (r * QLD + s * 8) * 2,
                 g_Ks2 + ((size_t)bh * 1024 + kt * 128 + r) * 192 + s * 8);
        }
        for (int i = tid; i < 64 * 16; i += 256) {
            const int r = i / 16, s = i % 16;
            cp16(sVh + (r * VLD + s * 8) * 2,
                 g_Vthi + ((size_t)bh * 64 + r) * 1024 + kt * 128 + s * 8);
            cp16(sVl + (r * VLD + s * 8) * 2,
                 g_Vtlo + ((size_t)bh * 64 + r) * 1024 + kt * 128 + s * 8);
        }
        CP_COMMIT();
        CP_WAIT(0);
        __syncthreads();

        float s_acc[16][4];
#pragma unroll
        for (int ni = 0; ni < 16; ni++)
#pragma unroll
            for (int r = 0; r < 4; r++) s_acc[ni][r] = 0.f;

#pragma unroll
        for (int ks = 0; ks < 12; ks++) {
            uint32_t a[4];
            LDSM_X4(a, sQ + ((wid * 16 + (lane & 15)) * QLD + ks * 16 + (lane >> 4) * 8) * 2);
            uint32_t bf[8][4];
            const int gg = lane >> 3;
#pragma unroll
            for (int np = 0; np < 8; np++) {
                const int row = np * 16 + (gg >> 1) * 8 + (lane & 7);
                LDSM_X4(bf[np], sK + (row * QLD + ks * 16 + (gg & 1) * 8) * 2);
            }
#pragma unroll
            for (int ni = 0; ni < 16; ni++)
                mma16816(s_acc[ni], a, &bf[ni >> 1][(ni & 1) * 2]);
        }

        float rm0 = -INFINITY, rm1 = -INFINITY;
#pragma unroll
        for (int ni = 0; ni < 16; ni++) {
            s_acc[ni][0] *= 0.125f; s_acc[ni][1] *= 0.125f;
            s_acc[ni][2] *= 0.125f; s_acc[ni][3] *= 0.125f;
            rm0 = fmaxf(rm0, fmaxf(s_acc[ni][0], s_acc[ni][1]));
            rm1 = fmaxf(rm1, fmaxf(s_acc[ni][2], s_acc[ni][3]));
        }
        rm0 = fmaxf(rm0, __shfl_xor_sync(0xffffffffu, rm0, 1));
        rm0 = fmaxf(rm0, __shfl_xor_sync(0xffffffffu, rm0, 2));
        rm1 = fmaxf(rm1, __shfl_xor_sync(0xffffffffu, rm1, 1));
        rm1 = fmaxf(rm1, __shfl_xor_sync(0xffffffffu, rm1, 2));

        const float nm0 = fmaxf(m0, rm0);
        const float nm1 = fmaxf(m1, rm1);
        const float a0 = __expf(m0 - nm0);
        const float a1 = __expf(m1 - nm1);

        float rs0 = 0.f, rs1 = 0.f;
#pragma unroll
        for (int ni = 0; ni < 16; ni++) {
            s_acc[ni][0] = __expf(s_acc[ni][0] - nm0);
            s_acc[ni][1] = __expf(s_acc[ni][1] - nm0);
            s_acc[ni][2] = __expf(s_acc[ni][2] - nm1);
            s_acc[ni][3] = __expf(s_acc[ni][3] - nm1);
            rs0 += s_acc[ni][0] + s_acc[ni][1];
            rs1 += s_acc[ni][2] + s_acc[ni][3];
        }
        rs0 += __shfl_xor_sync(0xffffffffu, rs0, 1);
        rs0 += __shfl_xor_sync(0xffffffffu, rs0, 2);
        rs1 += __shfl_xor_sync(0xffffffffu, rs1, 1);
        rs1 += __shfl_xor_sync(0xffffffffu, rs1, 2);

        l0 = l0 * a0 + rs0;  m0 = nm0;
        l1 = l1 * a1 + rs1;  m1 = nm1;

#pragma unroll
        for (int ni = 0; ni < 8; ni++) {
            acc_o[ni][0] *= a0; acc_o[ni][1] *= a0;
            acc_o[ni][2] *= a1; acc_o[ni][3] *= a1;
        }

        const int gg = lane >> 3;
#pragma unroll
        for (int ks = 0; ks < 8; ks++) {
            uint32_t ph[4], pl[4];
            {
                const float* t0 = s_acc[2 * ks];
                const float* t1 = s_acc[2 * ks + 1];
                ph[0] = packbf2(t0[0], t0[1]);
                ph[1] = packbf2(t0[2], t0[3]);
                ph[2] = packbf2(t1[0], t1[1]);
                ph[3] = packbf2(t1[2], t1[3]);
                __nv_bfloat162 hb;
                memcpy(&hb, &ph[0], 4);
                pl[0] = packbf2(t0[0] - __bfloat162float(hb.x), t0[1] - __bfloat162float(hb.y));
                memcpy(&hb, &ph[1], 4);
                pl[1] = packbf2(t0[2] - __bfloat162float(hb.x), t0[3] - __bfloat162float(hb.y));
                memcpy(&hb, &ph[2], 4);
                pl[2] = packbf2(t1[0] - __bfloat162float(hb.x), t1[1] - __bfloat162float(hb.y));
                memcpy(&hb, &ph[3], 4);
                pl[3] = packbf2(t1[2] - __bfloat162float(hb.x), t1[3] - __bfloat162float(hb.y));
            }
            uint32_t vh[4][4], vl[4][4];
#pragma unroll
            for (int np = 0; np < 4; np++) {
                const int row = np * 16 + (gg >> 1) * 8 + (lane & 7);
                const int col = ks * 16 + (gg & 1) * 8;
                LDSM_X4(vh[np], sVh + (row * VLD + col) * 2);
                LDSM_X4(vl[np], sVl + (row * VLD + col) * 2);
            }
#pragma unroll
            for (int ni = 0; ni < 8; ni++) {
                mma16816(acc_o[ni], ph, &vh[ni >> 1][(ni & 1) * 2]);
                mma16816(acc_o[ni], ph, &vl[ni >> 1][(ni & 1) * 2]);
                mma16816(acc_o[ni], pl, &vh[ni >> 1][(ni & 1) * 2]);
            }
        }
    }

    // ---- normalize and write split g_As directly: [hi|hi|lo] along KP ----
    const float inv0 = 1.0f / l0;
    const float inv1 = 1.0f / l1;
    const int row0 = qrow0 + wid * 16 + g;
#pragma unroll
    for (int ni = 0; ni < 8; ni++) {
        const int col = cbase + ni * 8 + (lane & 3) * 2;
        {
            const float v0 = acc_o[ni][0] * inv0;
            const float v1 = acc_o[ni][1] * inv0;
            const __nv_bfloat16 h0 = __float2bfloat16(v0);
            const __nv_bfloat16 h1 = __float2bfloat16(v1);
            const __nv_bfloat162 hi(h0, h1);
            const __nv_bfloat162 lo(__float2bfloat16(v0 - __bfloat162float(h0)),
                                    __float2bfloat16(v1 - __bfloat162float(h1)));
            __nv_bfloat16* rp = g_As + (size_t)row0 * KP;
            *(__nv_bfloat162*)(rp + col)        = hi;
            *(__nv_bfloat162*)(rp + 1024 + col) = hi;
            *(__nv_bfloat162*)(rp + 2048 + col) = lo;
        }
        {
            const float v0 = acc_o[ni][2] * inv1;
            const float v1 = acc_o[ni][3] * inv1;
            const __nv_bfloat16 h0 = __float2bfloat16(v0);
            const __nv_bfloat16 h1 = __float2bfloat16(v1);
            const __nv_bfloat162 hi(h0, h1);
            const __nv_bfloat162 lo(__float2bfloat16(v0 - __bfloat162float(h0)),
                                    __float2bfloat16(v1 - __bfloat162float(h1)));
            __nv_bfloat16* rp = g_As + (size_t)(row0 + 8) * KP;
            *(__nv_bfloat162*)(rp + col)        = hi;
            *(__nv_bfloat162*)(rp + 1024 + col) = hi;
            *(__nv_bfloat162*)(rp + 2048 + col) = lo;
        }
    }
}

// ---------------------------------------------------------------------------
// kernel_launch
// ---------------------------------------------------------------------------
extern "C" void kernel_launch(void* const* d_in, const int* in_sizes, int n_in,
                              void* d_out, int out_size)
{
    const float* x  = (const float*)d_in[0];
    const float* Wq = (const float*)d_in[1];
    const float* Wk = (const float*)d_in[2];
    const float* Wv = (const float*)d_in[3];
    const float* Wo = (const float*)d_in[4];
    const float* bo = (const float*)d_in[5];
    float* out = (float*)d_out;

    cudaFuncSetAttribute(qkv_hmma_kernel, cudaFuncAttributeMaxDynamicSharedMemorySize, GEMM_SMEM);
    cudaFuncSetAttribute(out_hmma_kernel, cudaFuncAttributeMaxDynamicSharedMemorySize, GEMM_SMEM);
    cudaFuncSetAttribute(attn_hmma_kernel, cudaFuncAttributeMaxDynamicSharedMemorySize, ATTN_SMEM);

    // 1) split conversions for projections
    {
        const int nx = M_ROWS * K_DIM / 4;
        conv_x_kernel<<<(nx + 255) / 256, 256>>>(x);
        const int nw = N_DIM * K_DIM / 4;
        conv_w_kernel<<<dim3((nw + 255) / 256, 1, 4), 256>>>(Wq, Wk, Wv, Wo);
    }

    // 2) QKV projections (HMMA v2)
    qkv_hmma_kernel<<<dim3(N_DIM / GBN, M_ROWS / GBM, 3), 256, GEMM_SMEM>>>();

    // 3) attention operand conversions
    conv_qk_kernel<<<(M_ROWS * 256) / 256, 256>>>();
    conv_vt_kernel<<<64 * 16, 256>>>();

    // 4) attention (HMMA flash, split precision; writes g_As directly)
    attn_hmma_kernel<<<dim3(8, 64), 256, ATTN_SMEM>>>();

    // 5) output projection + bias (HMMA v2)
    out_hmma_kernel<<<dim3(N_DIM / GBN, M_ROWS / GBM), 256, GEMM_SMEM>>>(bo, out);
}

// round 7
// speedup vs baseline: 2.6103x; 1.2720x over previous
#include <cuda_runtime.h>
#include <cuda_bf16.h>
#include <cuda_fp16.h>
#include <math.h>
#include <stdint.h>
#include <string.h>

// ---------------------------------------------------------------------------
// Problem constants
// ---------------------------------------------------------------------------
#define M_ROWS 4096
#define K_DIM  1024
#define N_DIM  1024
#define HEADS  16
#define DHEAD  64
#define TSEQ   1024
#define BATCH  4

// fp16 2-product widened K for projections: A' = [xh|xh], B' = [Whi|Wlo]
#define KP2    2048

// fp32 scratch (attention inputs)
__device__ float g_Q[M_ROWS * K_DIM];
__device__ float g_K[M_ROWS * K_DIM];
__device__ float g_V[M_ROWS * K_DIM];

// fp16 scratch for projection GEMMs
__device__ __align__(16) __half g_xs[M_ROWS * KP2];
__device__ __align__(16) __half g_As[M_ROWS * KP2];
__device__ __align__(16) __half g_Ws[4 * N_DIM * KP2];

// attention split operands (bf16 3-product, unchanged)
__device__ __align__(16) __nv_bfloat16 g_Qs2[64 * 1024 * 192];
__device__ __align__(16) __nv_bfloat16 g_Ks2[64 * 1024 * 192];
__device__ __align__(16) __nv_bfloat16 g_Vthi[64 * 64 * 1024];
__device__ __align__(16) __nv_bfloat16 g_Vtlo[64 * 64 * 1024];

// ---------------------------------------------------------------------------
// PTX helpers
// ---------------------------------------------------------------------------
__device__ __forceinline__ uint32_t smem_u32(const void* p) {
    uint32_t a;
    asm("{ .reg .u64 t; cvta.to.shared.u64 t, %1; cvt.u32.u64 %0, t; }"
        : "=r"(a) : "l"(p));
    return a;
}
__device__ __forceinline__ void cp16(uint32_t s, const void* g) {
    asm volatile("cp.async.cg.shared.global [%0], [%1], 16;" :: "r"(s), "l"(g));
}
#define CP_COMMIT() asm volatile("cp.async.commit_group;" ::: "memory")
#define CP_WAIT(n)  asm volatile("cp.async.wait_group %0;" :: "n"(n) : "memory")

#define LDSM_X4(r, addr)                                                       \
    asm volatile("ldmatrix.sync.aligned.m8n8.x4.shared.b16 {%0,%1,%2,%3}, [%4];" \
                 : "=r"((r)[0]), "=r"((r)[1]), "=r"((r)[2]), "=r"((r)[3])      \
                 : "r"(addr))

__device__ __forceinline__ void mma16816bf(float* c, const uint32_t* a,
                                           const uint32_t* b) {
    asm volatile(
        "mma.sync.aligned.m16n8k16.row.col.f32.bf16.bf16.f32 "
        "{%0,%1,%2,%3}, {%4,%5,%6,%7}, {%8,%9}, {%0,%1,%2,%3};"
        : "+f"(c[0]), "+f"(c[1]), "+f"(c[2]), "+f"(c[3])
        : "r"(a[0]), "r"(a[1]), "r"(a[2]), "r"(a[3]), "r"(b[0]), "r"(b[1]));
}
__device__ __forceinline__ void mma16816h(float* c, const uint32_t* a,
                                          const uint32_t* b) {
    asm volatile(
        "mma.sync.aligned.m16n8k16.row.col.f32.f16.f16.f32 "
        "{%0,%1,%2,%3}, {%4,%5,%6,%7}, {%8,%9}, {%0,%1,%2,%3};"
        : "+f"(c[0]), "+f"(c[1]), "+f"(c[2]), "+f"(c[3])
        : "r"(a[0]), "r"(a[1]), "r"(a[2]), "r"(a[3]), "r"(b[0]), "r"(b[1]));
}

__device__ __forceinline__ uint32_t packbf2(float x, float y) {
    __nv_bfloat162 t = __floats2bfloat162_rn(x, y);
    uint32_t u;
    memcpy(&u, &t, 4);
    return u;
}

// ---------------------------------------------------------------------------
// HMMA fp16 NT GEMM: C[M,N] = A'[M,KP2] @ B'[N,KP2]^T (+ bias)
// CTA 128x128, BK=64, 3-stage cp.async, swizzled smem, 2 CTAs/SM.
// ---------------------------------------------------------------------------
#define GBM 128
#define GBN 128
#define GBK 64
#define TILE_B  (128 * 128)
#define STAGE_B (2 * TILE_B)
#define NSTAGE  3
#define NCH     (KP2 / GBK)              // 32
#define GEMM_SMEM (NSTAGE * STAGE_B)     // 98304

__device__ __forceinline__ uint32_t swz(uint32_t row, uint32_t seg) {
    return row * 128 + ((seg ^ (row & 7)) * 16);
}

__device__ __forceinline__ void load_chunk(const __half* __restrict__ A,
                                           const __half* __restrict__ B,
                                           int bm, int bn, int k0,
                                           uint32_t sA, uint32_t sB) {
    const int tid = threadIdx.x;
    const int row = tid >> 1;
    const int sb  = (tid & 1) * 4;
#pragma unroll
    for (int j = 0; j < 4; j++) {
        const int seg = sb + j;
        cp16(sA + swz(row, seg), A + (size_t)(bm + row) * KP2 + k0 + seg * 8);
        cp16(sB + swz(row, seg), B + (size_t)(bn + row) * KP2 + k0 + seg * 8);
    }
    CP_COMMIT();
}

__device__ void gemm_hmma_body(const __half* __restrict__ A,
                               const __half* __restrict__ B,
                               const float* __restrict__ bias,
                               float* __restrict__ C) {
    extern __shared__ char sm[];
    const uint32_t smb = smem_u32(sm);

    const int tid  = threadIdx.x;
    const int wid  = tid >> 5;
    const int lane = tid & 31;
    const int wm   = wid >> 2;
    const int wn   = wid & 3;
    const int bm   = blockIdx.y * GBM;
    const int bn   = blockIdx.x * GBN;

    float acc[4][4][4];
#pragma unroll
    for (int i = 0; i < 4; i++)
#pragma unroll
        for (int j = 0; j < 4; j++)
#pragma unroll
            for (int r = 0; r < 4; r++) acc[i][j][r] = 0.f;

#pragma unroll
    for (int s = 0; s < NSTAGE; s++)
        load_chunk(A, B, bm, bn, s * GBK,
                   smb + s * STAGE_B, smb + s * STAGE_B + TILE_B);

    for (int c = 0; c < NCH; c++) {
        const int rem = NCH - 1 - c;
        if (rem >= 2)      CP_WAIT(2);
        else if (rem == 1) CP_WAIT(1);
        else               CP_WAIT(0);
        __syncthreads();

        const uint32_t aB = smb + (c % NSTAGE) * STAGE_B;
        const uint32_t bB = aB + TILE_B;

#pragma unroll
        for (int ks = 0; ks < 4; ks++) {
            uint32_t afr[4][4];
#pragma unroll
            for (int mi = 0; mi < 4; mi++) {
                const int row = wm * 64 + mi * 16 + (lane & 15);
                const int seg = ks * 2 + (lane >> 4);
                LDSM_X4(afr[mi], aB + swz(row, seg));
            }
            uint32_t bfr[2][4];
            const int g = lane >> 3;
#pragma unroll
            for (int np = 0; np < 2; np++) {
                const int row = wn * 32 + np * 16 + (g >> 1) * 8 + (lane & 7);
                const int seg = ks * 2 + (g & 1);
                LDSM_X4(bfr[np], bB + swz(row, seg));
            }
#pragma unroll
            for (int mi = 0; mi < 4; mi++) {
#pragma unroll
                for (int ni = 0; ni < 4; ni++)
                    mma16816h(acc[mi][ni], afr[mi], &bfr[ni >> 1][(ni & 1) * 2]);
            }
        }
        __syncthreads();

        if (c + NSTAGE < NCH)
            load_chunk(A, B, bm, bn, (c + NSTAGE) * GBK,
                       smb + (c % NSTAGE) * STAGE_B,
                       smb + (c % NSTAGE) * STAGE_B + TILE_B);
    }

#pragma unroll
    for (int mi = 0; mi < 4; mi++) {
#pragma unroll
        for (int ni = 0; ni < 4; ni++) {
            const int r0 = bm + wm * 64 + mi * 16 + (lane >> 2);
            const int c0 = bn + wn * 32 + ni * 8 + (lane & 3) * 2;
            float2 v0 = make_float2(acc[mi][ni][0], acc[mi][ni][1]);
            float2 v1 = make_float2(acc[mi][ni][2], acc[mi][ni][3]);
            if (bias) {
                const float b0 = bias[c0], b1 = bias[c0 + 1];
                v0.x += b0; v0.y += b1;
                v1.x += b0; v1.y += b1;
            }
            *(float2*)&C[(size_t)r0 * N_DIM + c0]       = v0;
            *(float2*)&C[(size_t)(r0 + 8) * N_DIM + c0] = v1;
        }
    }
}

__global__ __launch_bounds__(256, 2) void qkv_hmma_kernel() {
    const int z = blockIdx.z;
    float* C = (z == 0) ? g_Q : (z == 1) ? g_K : g_V;
    gemm_hmma_body(g_xs, g_Ws + (size_t)z * N_DIM * KP2, nullptr, C);
}

__global__ __launch_bounds__(256, 2) void out_hmma_kernel(const float* __restrict__ bo,
                                                          float* __restrict__ out) {
    gemm_hmma_body(g_As, g_Ws + (size_t)3 * N_DIM * KP2, bo, out);
}

// ---------------------------------------------------------------------------
// conversions
// ---------------------------------------------------------------------------
// x -> fp16 A' = [xh | xh]
__global__ void conv_x_kernel(const float* __restrict__ src) {
    const int i = blockIdx.x * blockDim.x + threadIdx.x;
    if (i >= M_ROWS * K_DIM / 4) return;
    const int r = i / (K_DIM / 4);
    const int k4 = (i % (K_DIM / 4)) * 4;
    float4 v = ((const float4*)src)[i];
    const __half2 h0 = __floats2half2_rn(v.x, v.y);
    const __half2 h1 = __floats2half2_rn(v.z, v.w);
    __half2* d0 = (__half2*)(g_xs + (size_t)r * KP2 + k4);
    __half2* d1 = (__half2*)(g_xs + (size_t)r * KP2 + 1024 + k4);
    d0[0] = h0; d0[1] = h1;
    d1[0] = h0; d1[1] = h1;
}

// W -> fp16 B' = [Whi | Wlo]
__global__ void conv_w_kernel(const float* __restrict__ Wq, const float* __restrict__ Wk,
                              const float* __restrict__ Wv, const float* __restrict__ Wo) {
    const int z = blockIdx.z;
    const float* src = (z == 0) ? Wq : (z == 1) ? Wk : (z == 2) ? Wv : Wo;
    const int i = blockIdx.x * blockDim.x + threadIdx.x;
    if (i >= N_DIM * K_DIM / 4) return;
    const int n = i / (K_DIM / 4);
    const int k4 = (i % (K_DIM / 4)) * 4;
    float4 v = ((const float4*)src)[i];
    const __half hx = __float2half_rn(v.x);
    const __half hy = __float2half_rn(v.y);
    const __half hz = __float2half_rn(v.z);
    const __half hw = __float2half_rn(v.w);
    __half* dst = g_Ws + (size_t)z * N_DIM * KP2;
    __half2* d0 = (__half2*)(dst + (size_t)n * KP2 + k4);
    __half2* d1 = (__half2*)(dst + (size_t)n * KP2 + 1024 + k4);
    d0[0] = __half2(hx, hy);
    d0[1] = __half2(hz, hw);
    d1[0] = __half2(__float2half_rn(v.x - __half2float(hx)),
                    __float2half_rn(v.y - __half2float(hy)));
    d1[1] = __half2(__float2half_rn(v.z - __half2float(hz)),
                    __float2half_rn(v.w - __half2float(hw)));
}

// bf16 split helpers for attention operands (unchanged)
__device__ __forceinline__ void split4(const float4 v, __nv_bfloat162* h,
                                       __nv_bfloat162* l) {
    const __nv_bfloat16 h0 = __float2bfloat16(v.x);
    const __nv_bfloat16 h1 = __float2bfloat16(v.y);
    const __nv_bfloat16 h2 = __float2bfloat16(v.z);
    const __nv_bfloat16 h3 = __float2bfloat16(v.w);
    h[0] = __nv_bfloat162(h0, h1);
    h[1] = __nv_bfloat162(h2, h3);
    l[0] = __nv_bfloat162(__float2bfloat16(v.x - __bfloat162float(h0)),
                          __float2bfloat16(v.y - __bfloat162float(h1)));
    l[1] = __nv_bfloat162(__float2bfloat16(v.z - __bfloat162float(h2)),
                          __float2bfloat16(v.w - __bfloat162float(h3)));
}

// Q'[bh][t][192] = [hi|hi|lo],  K'[bh][t][192] = [hi|lo|hi]
__global__ void conv_qk_kernel() {
    const int i = blockIdx.x * blockDim.x + threadIdx.x;
    if (i >= M_ROWS * 256) return;
    const int row = i >> 8;
    const int e4  = i & 255;
    const int h   = e4 >> 4;
    const int dd  = (e4 & 15) * 4;
    const int b   = row >> 10, t = row & 1023;
    const size_t base = ((size_t)((b * 16 + h) * 1024) + t) * 192;

    float4 q = *(const float4*)&g_Q[(size_t)row * K_DIM + h * 64 + dd];
    float4 k = *(const float4*)&g_K[(size_t)row * K_DIM + h * 64 + dd];
    __nv_bfloat162 qh[2], ql[2], kh[2], kl[2];
    split4(q, qh, ql);
    split4(k, kh, kl);

    __nv_bfloat162* p;
    p = (__nv_bfloat162*)(g_Qs2 + base + dd);        p[0] = qh[0]; p[1] = qh[1];
    p = (__nv_bfloat162*)(g_Qs2 + base + 64 + dd);   p[0] = qh[0]; p[1] = qh[1];
    p = (__nv_bfloat162*)(g_Qs2 + base + 128 + dd);  p[0] = ql[0]; p[1] = ql[1];

    p = (__nv_bfloat162*)(g_Ks2 + base + dd);        p[0] = kh[0]; p[1] = kh[1];
    p = (__nv_bfloat162*)(g_Ks2 + base + 64 + dd);   p[0] = kl[0]; p[1] = kl[1];
    p = (__nv_bfloat162*)(g_Ks2 + base + 128 + dd);  p[0] = kh[0]; p[1] = kh[1];
}

__global__ void conv_vt_kernel() {
    __shared__ float vs[64][68];
    const int blk = blockIdx.x;
    const int bh = blk >> 4, tt = blk & 15;
    const int b = bh >> 4, h = bh & 15;
    const int t0 = tt * 64;
    const int tid = threadIdx.x;

    const int r  = tid >> 4;
    const int c4 = (tid & 15) * 4;
#pragma unroll
    for (int j = 0; j < 4; j++) {
        const int t = r + j * 16;
        float4 v = *(const float4*)&g_V[(size_t)(b * 1024 + t0 + t) * K_DIM + h * 64 + c4];
        vs[t][c4 + 0] = v.x; vs[t][c4 + 1] = v.y;
        vs[t][c4 + 2] = v.z; vs[t][c4 + 3] = v.w;
    }
    __syncthreads();

    const int d  = tid >> 2;
    const int ts = (tid & 3) * 16;
    const size_t obase = ((size_t)bh * 64 + d) * 1024 + t0 + ts;
#pragma unroll
    for (int j = 0; j < 16; j += 2) {
        const float v0 = vs[ts + j][d];
        const float v1 = vs[ts + j + 1][d];
        const __nv_bfloat16 h0 = __float2bfloat16(v0);
        const __nv_bfloat16 h1 = __float2bfloat16(v1);
        *(__nv_bfloat162*)&g_Vthi[obase + j] = __nv_bfloat162(h0, h1);
        *(__nv_bfloat162*)&g_Vtlo[obase + j] =
            __nv_bfloat162(__float2bfloat16(v0 - __bfloat162float(h0)),
                           __float2bfloat16(v1 - __bfloat162float(h1)));
    }
}

// ---------------------------------------------------------------------------
// HMMA flash attention (bf16 3-product) — epilogue writes fp16 A' = [Ah|Ah]
// ---------------------------------------------------------------------------
#define QLD 200
#define VLD 136
#define ATTN_SMEM (2 * 128 * QLD * 2 + 2 * 64 * VLD * 2)

__global__ __launch_bounds__(256) void attn_hmma_kernel()
{
    extern __shared__ char sm[];
    const uint32_t smb = smem_u32(sm);
    const uint32_t sQ  = smb;
    const uint32_t sK  = smb + 128 * QLD * 2;
    const uint32_t sVh = smb + 2 * 128 * QLD * 2;
    const uint32_t sVl = sVh + 64 * VLD * 2;

    const int tid  = threadIdx.x;
    const int wid  = tid >> 5;
    const int lane = tid & 31;
    const int g    = lane >> 2;
    const int qt   = blockIdx.x;
    const int bh   = blockIdx.y;
    const int b    = bh >> 4;
    const int h    = bh & 15;
    const int cbase = h * DHEAD;
    const int qrow0 = b * TSEQ + qt * 128;

    for (int i = tid; i < 128 * 24; i += 256) {
        const int r = i / 24, s = i % 24;
        cp16(sQ + (r * QLD + s * 8) * 2,
             g_Qs2 + ((size_t)bh * 1024 + qt * 128 + r) * 192 + s * 8);
    }
    CP_COMMIT();

    float acc_o[8][4];
#pragma unroll
    for (int i = 0; i < 8; i++)
#pragma unroll
        for (int r = 0; r < 4; r++) acc_o[i][r] = 0.f;
    float m0 = -INFINITY, m1 = -INFINITY, l0 = 0.f, l1 = 0.f;

    for (int kt = 0; kt < 8; kt++) {
        __syncthreads();
        for (int i = tid; i < 128 * 24; i += 256) {
            const int r = i / 24, s = i % 24;
            cp16(sK + (r * QLD + s * 8) * 2,
                 g_Ks2 + ((size_t)bh * 1024 + kt * 128 + r) * 192 + s * 8);
        }
        for (int i = tid; i < 64 * 16; i += 256) {
            const int r = i / 16, s = i % 16;
            cp16(sVh + (r * VLD + s * 8) * 2,
                 g_Vthi + ((size_t)bh * 64 + r) * 1024 + kt * 128 + s * 8);
            cp16(sVl + (r * VLD + s * 8) * 2,
                 g_Vtlo + ((size_t)bh * 64 + r) * 1024 + kt * 128 + s * 8);
        }
        CP_COMMIT();
        CP_WAIT(0);
        __syncthreads();

        float s_acc[16][4];
#pragma unroll
        for (int ni = 0; ni < 16; ni++)
#pragma unroll
            for (int r = 0; r < 4; r++) s_acc[ni][r] = 0.f;

#pragma unroll
        for (int ks = 0; ks < 12; ks++) {
            uint32_t a[4];
            LDSM_X4(a, sQ + ((wid * 16 + (lane & 15)) * QLD + ks * 16 + (lane >> 4) * 8) * 2);
            uint32_t bf[8][4];
            const int gg = lane >> 3;
#pragma unroll
            for (int np = 0; np < 8; np++) {
                const int row = np * 16 + (gg >> 1) * 8 + (lane & 7);
                LDSM_X4(bf[np], sK + (row * QLD + ks * 16 + (gg & 1) * 8) * 2);
            }
#pragma unroll
            for (int ni = 0; ni < 16; ni++)
                mma16816bf(s_acc[ni], a, &bf[ni >> 1][(ni & 1) * 2]);
        }

        float rm0 = -INFINITY, rm1 = -INFINITY;
#pragma unroll
        for (int ni = 0; ni < 16; ni++) {
            s_acc[ni][0] *= 0.125f; s_acc[ni][1] *= 0.125f;
            s_acc[ni][2] *= 0.125f; s_acc[ni][3] *= 0.125f;
            rm0 = fmaxf(rm0, fmaxf(s_acc[ni][0], s_acc[ni][1]));
            rm1 = fmaxf(rm1, fmaxf(s_acc[ni][2], s_acc[ni][3]));
        }
        rm0 = fmaxf(rm0, __shfl_xor_sync(0xffffffffu, rm0, 1));
        rm0 = fmaxf(rm0, __shfl_xor_sync(0xffffffffu, rm0, 2));
        rm1 = fmaxf(rm1, __shfl_xor_sync(0xffffffffu, rm1, 1));
        rm1 = fmaxf(rm1, __shfl_xor_sync(0xffffffffu, rm1, 2));

        const float nm0 = fmaxf(m0, rm0);
        const float nm1 = fmaxf(m1, rm1);
        const float a0 = __expf(m0 - nm0);
        const float a1 = __expf(m1 - nm1);

        float rs0 = 0.f, rs1 = 0.f;
#pragma unroll
        for (int ni = 0; ni < 16; ni++) {
            s_acc[ni][0] = __expf(s_acc[ni][0] - nm0);
            s_acc[ni][1] = __expf(s_acc[ni][1] - nm0);
            s_acc[ni][2] = __expf(s_acc[ni][2] - nm1);
            s_acc[ni][3] = __expf(s_acc[ni][3] - nm1);
            rs0 += s_acc[ni][0] + s_acc[ni][1];
            rs1 += s_acc[ni][2] + s_acc[ni][3];
        }
        rs0 += __shfl_xor_sync(0xffffffffu, rs0, 1);
        rs0 += __shfl_xor_sync(0xffffffffu, rs0, 2);
        rs1 += __shfl_xor_sync(0xffffffffu, rs1, 1);
        rs1 += __shfl_xor_sync(0xffffffffu, rs1, 2);

        l0 = l0 * a0 + rs0;  m0 = nm0;
        l1 = l1 * a1 + rs1;  m1 = nm1;

#pragma unroll
        for (int ni = 0; ni < 8; ni++) {
            acc_o[ni][0] *= a0; acc_o[ni][1] *= a0;
            acc_o[ni][2] *= a1; acc_o[ni][3] *= a1;
        }

        const int gg = lane >> 3;
#pragma unroll
        for (int ks = 0; ks < 8; ks++) {
            uint32_t ph[4], pl[4];
            {
                const float* t0 = s_acc[2 * ks];
                const float* t1 = s_acc[2 * ks + 1];
                ph[0] = packbf2(t0[0], t0[1]);
                ph[1] = packbf2(t0[2], t0[3]);
                ph[2] = packbf2(t1[0], t1[1]);
                ph[3] = packbf2(t1[2], t1[3]);
                __nv_bfloat162 hb;
                memcpy(&hb, &ph[0], 4);
                pl[0] = packbf2(t0[0] - __bfloat162float(hb.x), t0[1] - __bfloat162float(hb.y));
                memcpy(&hb, &ph[1], 4);
                pl[1] = packbf2(t0[2] - __bfloat162float(hb.x), t0[3] - __bfloat162float(hb.y));
                memcpy(&hb, &ph[2], 4);
                pl[2] = packbf2(t1[0] - __bfloat162float(hb.x), t1[1] - __bfloat162float(hb.y));
                memcpy(&hb, &ph[3], 4);
                pl[3] = packbf2(t1[2] - __bfloat162float(hb.x), t1[3] - __bfloat162float(hb.y));
            }
            uint32_t vh[4][4], vl[4][4];
#pragma unroll
            for (int np = 0; np < 4; np++) {
                const int row = np * 16 + (gg >> 1) * 8 + (lane & 7);
                const int col = ks * 16 + (gg & 1) * 8;
                LDSM_X4(vh[np], sVh + (row * VLD + col) * 2);
                LDSM_X4(vl[np], sVl + (row * VLD + col) * 2);
            }
#pragma unroll
            for (int ni = 0; ni < 8; ni++) {
                mma16816bf(acc_o[ni], ph, &vh[ni >> 1][(ni & 1) * 2]);
                mma16816bf(acc_o[ni], ph, &vl[ni >> 1][(ni & 1) * 2]);
                mma16816bf(acc_o[ni], pl, &vh[ni >> 1][(ni & 1) * 2]);
            }
        }
    }

    // ---- normalize and write fp16 A' = [Ah | Ah] ----
    const float inv0 = 1.0f / l0;
    const float inv1 = 1.0f / l1;
    const int row0 = qrow0 + wid * 16 + g;
#pragma unroll
    for (int ni = 0; ni < 8; ni++) {
        const int col = cbase + ni * 8 + (lane & 3) * 2;
        {
            const __half2 hv = __floats2half2_rn(acc_o[ni][0] * inv0,
                                                 acc_o[ni][1] * inv0);
            __half* rp = g_As + (size_t)row0 * KP2;
            *(__half2*)(rp + col)        = hv;
            *(__half2*)(rp + 1024 + col) = hv;
        }
        {
            const __half2 hv = __floats2half2_rn(acc_o[ni][2] * inv1,
                                                 acc_o[ni][3] * inv1);
            __half* rp = g_As + (size_t)(row0 + 8) * KP2;
            *(__half2*)(rp + col)        = hv;
            *(__half2*)(rp + 1024 + col) = hv;
        }
    }
}

// ---------------------------------------------------------------------------
// kernel_launch
// ---------------------------------------------------------------------------
extern "C" void kernel_launch(void* const* d_in, const int* in_sizes, int n_in,
                              void* d_out, int out_size)
{
    const float* x  = (const float*)d_in[0];
    const float* Wq = (const float*)d_in[1];
    const float* Wk = (const float*)d_in[2];
    const float* Wv = (const float*)d_in[3];
    const float* Wo = (const float*)d_in[4];
    const float* bo = (const float*)d_in[5];
    float* out = (float*)d_out;

    cudaFuncSetAttribute(qkv_hmma_kernel, cudaFuncAttributeMaxDynamicSharedMemorySize, GEMM_SMEM);
    cudaFuncSetAttribute(out_hmma_kernel, cudaFuncAttributeMaxDynamicSharedMemorySize, GEMM_SMEM);
    cudaFuncSetAttribute(attn_hmma_kernel, cudaFuncAttributeMaxDynamicSharedMemorySize, ATTN_SMEM);

    // 1) conversions for projections (fp16 2-product)
    {
        const int nx = M_ROWS * K_DIM / 4;
        conv_x_kernel<<<(nx + 255) / 256, 256>>>(x);
        const int nw = N_DIM * K_DIM / 4;
        conv_w_kernel<<<dim3((nw + 255) / 256, 1, 4), 256>>>(Wq, Wk, Wv, Wo);
    }

    // 2) QKV projections (fp16 HMMA)
    qkv_hmma_kernel<<<dim3(N_DIM / GBN, M_ROWS / GBM, 3), 256, GEMM_SMEM>>>();

    // 3) attention operand conversions (bf16 split)
    conv_qk_kernel<<<(M_ROWS * 256) / 256, 256>>>();
    conv_vt_kernel<<<64 * 16, 256>>>();

    // 4) attention (bf16 3-product HMMA flash; writes fp16 g_As)
    attn_hmma_kernel<<<dim3(8, 64), 256, ATTN_SMEM>>>();

    // 5) output projection + bias (fp16 HMMA)
    out_hmma_kernel<<<dim3(N_DIM / GBN, M_ROWS / GBM), 256, GEMM_SMEM>>>(bo, out);
}